// round 2
// baseline (speedup 1.0000x reference)
#include <cuda_runtime.h>

#define BATCH 8
#define CCH   256
#define DQK   32
#define NPIX  4096
#define PROWS 320
#define TQ    64
#define TK    64
#define NQT   (NPIX/TQ)            /* 64 */
#define NCTA_ATTN (BATCH*NQT)      /* 512 */

__device__ __align__(16) float g_proj[(size_t)BATCH*PROWS*NPIX]; /* rows: 0-31 q, 32-63 k, 64-319 v */
__device__ __align__(16) float g_y[(size_t)BATCH*CCH*NPIX];
__device__ __align__(16) float g_psum[NCTA_ATTN*CCH];
__device__ __align__(16) float g_psq[NCTA_ATTN*CCH];
__device__ __align__(16) float g_bn[2*CCH];

// ---------------------------------------------------------------------------
// Kernel A: fused projection GEMM.  out[b][row][n] = W[row] . x[b][:][n] + bias
// W stacked: rows 0..31 = wq, 32..63 = wk, 64..319 = wv.
// Tile: 64 rows x 128 cols per CTA, K-step 32, 256 threads, 32 outputs/thread.
// ---------------------------------------------------------------------------
__global__ __launch_bounds__(256) void proj_kernel(
    const float* __restrict__ x,
    const float* __restrict__ wq, const float* __restrict__ bq,
    const float* __restrict__ wk, const float* __restrict__ bk,
    const float* __restrict__ wv, const float* __restrict__ bv)
{
    __shared__ float Wt[32*64];    // [kk][row]
    __shared__ float Xt[32*128];   // [kk][col]
    const int t  = threadIdx.x;
    const int nt = blockIdx.x;     // 0..31  col tile
    const int rt = blockIdx.y;     // 0..4   row tile
    const int b  = blockIdx.z;     // 0..7
    const int n0 = nt*128;
    const int rowbase = rt*64;
    const int cg = t & 31;         // col group
    const int rg = t >> 5;         // row group (warp id)
    const int col = cg*4;
    const float* xb = x + (size_t)b*CCH*NPIX;

    float4 acc[8];
    #pragma unroll
    for (int i=0;i<8;i++) acc[i] = make_float4(0.f,0.f,0.f,0.f);

    for (int k0=0;k0<CCH;k0+=32){
        __syncthreads();
        // load W tile (transposed into [kk][row])
        #pragma unroll
        for (int i=0;i<2;i++){
            int idx = t*2+i;               // 0..511 float4 chunks
            int r   = idx >> 3;            // 0..63 local row
            int kc  = idx & 7;             // 0..7  k-chunk
            int grow = rowbase + r;
            const float* wsrc;
            int lrow;
            if (grow < 32)      { wsrc = wq; lrow = grow; }
            else if (grow < 64) { wsrc = wk; lrow = grow-32; }
            else                { wsrc = wv; lrow = grow-64; }
            float4 wv4 = *(const float4*)(wsrc + (size_t)lrow*CCH + k0 + kc*4);
            Wt[(kc*4+0)*64 + r] = wv4.x;
            Wt[(kc*4+1)*64 + r] = wv4.y;
            Wt[(kc*4+2)*64 + r] = wv4.z;
            Wt[(kc*4+3)*64 + r] = wv4.w;
        }
        // load X tile [kk][128]
        #pragma unroll
        for (int i=0;i<4;i++){
            int idx = i*256 + t;           // 0..1023 float4
            int kk  = idx >> 5;
            int cc  = (idx & 31)*4;
            float4 xv = *(const float4*)(xb + (size_t)(k0+kk)*NPIX + n0 + cc);
            *(float4*)&Xt[kk*128 + cc] = xv;
        }
        __syncthreads();
        #pragma unroll
        for (int kk=0;kk<32;kk++){
            float4 xv = *(float4*)&Xt[kk*128 + col];
            float4 wa = *(float4*)&Wt[kk*64 + rg*8];
            float4 wb = *(float4*)&Wt[kk*64 + rg*8 + 4];
            float wr[8] = {wa.x,wa.y,wa.z,wa.w,wb.x,wb.y,wb.z,wb.w};
            #pragma unroll
            for (int i=0;i<8;i++){
                acc[i].x += wr[i]*xv.x;
                acc[i].y += wr[i]*xv.y;
                acc[i].z += wr[i]*xv.z;
                acc[i].w += wr[i]*xv.w;
            }
        }
    }
    // epilogue with bias
    #pragma unroll
    for (int i=0;i<8;i++){
        int grow = rowbase + rg*8 + i;
        float bias;
        if (grow < 32)      bias = bq[grow];
        else if (grow < 64) bias = bk[grow-32];
        else                bias = bv[grow-64];
        float4 o = acc[i];
        o.x += bias; o.y += bias; o.z += bias; o.w += bias;
        *(float4*)(g_proj + ((size_t)b*PROWS + grow)*NPIX + n0 + col) = o;
    }
}

// ---------------------------------------------------------------------------
// Kernel B: flash attention + gamma*out + x + deterministic BN partials.
// 512 CTAs (b, qtile), 256 threads, ~99KB dynamic smem.
// ---------------------------------------------------------------------------
__global__ __launch_bounds__(256) void attn_kernel(
    const float* __restrict__ x, const float* __restrict__ gamma)
{
    extern __shared__ float sm[];
    float* Qs     = sm;            // [32][64]   d-major
    float* Ks     = sm + 2048;     // [32][64]
    float* Vs     = sm + 4096;     // [256][64]  c-major
    float* Ss     = sm + 20480;    // [64][65]   row-major, pad 1
    float* row_m  = sm + 24640;    // [64]
    float* row_l  = sm + 24704;    // [64]
    float* row_sc = sm + 24768;    // [64]

    const int t  = threadIdx.x;
    const int b  = blockIdx.y;
    const int i0 = blockIdx.x * TQ;
    const float* qg = g_proj + (size_t)b*PROWS*NPIX;
    const float* kg = qg + (size_t)32*NPIX;
    const float* vg = qg + (size_t)64*NPIX;

    // load Q tile (stays resident)
    #pragma unroll
    for (int i=0;i<2;i++){
        int idx = i*256+t;
        int d = idx>>4, rc = (idx&15)<<2;
        *(float4*)&Qs[d*64+rc] = *(const float4*)(qg + (size_t)d*NPIX + i0 + rc);
    }
    if (t < 64){ row_m[t] = -1e30f; row_l[t] = 0.f; }

    float acc[4][16];
    #pragma unroll
    for (int u=0;u<4;u++)
        #pragma unroll
        for (int c=0;c<16;c++) acc[u][c] = 0.f;

    const int l = t & 31, w = t >> 5;
    const int srow = w*8 + (l>>2);   // softmax row owned (with 3 sibling lanes)
    const int sjb  = (l&3)*16;       // 16 cols of that row
    const int org  = (t&15)*4;       // O: 4 rows base
    const int occ  = (t>>4)*16;      // O: 16 channels base

    for (int j0=0;j0<NPIX;j0+=TK){
        __syncthreads();
        #pragma unroll
        for (int i=0;i<2;i++){
            int idx=i*256+t; int d=idx>>4, rc=(idx&15)<<2;
            *(float4*)&Ks[d*64+rc] = *(const float4*)(kg + (size_t)d*NPIX + j0 + rc);
        }
        #pragma unroll
        for (int i=0;i<16;i++){
            int idx=i*256+t; int c=idx>>4, rc=(idx&15)<<2;
            *(float4*)&Vs[c*64+rc] = *(const float4*)(vg + (size_t)c*NPIX + j0 + rc);
        }
        __syncthreads();

        // ---- S = Q.K for 16 entries of one row ----
        float s[16];
        #pragma unroll
        for (int i=0;i<16;i++) s[i]=0.f;
        #pragma unroll
        for (int d=0; d<DQK; d++){
            float qv = Qs[d*64 + srow];
            float4 k0v = *(const float4*)&Ks[d*64 + sjb];
            float4 k1v = *(const float4*)&Ks[d*64 + sjb + 4];
            float4 k2v = *(const float4*)&Ks[d*64 + sjb + 8];
            float4 k3v = *(const float4*)&Ks[d*64 + sjb + 12];
            s[0] += qv*k0v.x;  s[1] += qv*k0v.y;  s[2] += qv*k0v.z;  s[3] += qv*k0v.w;
            s[4] += qv*k1v.x;  s[5] += qv*k1v.y;  s[6] += qv*k1v.z;  s[7] += qv*k1v.w;
            s[8] += qv*k2v.x;  s[9] += qv*k2v.y;  s[10]+= qv*k2v.z;  s[11]+= qv*k2v.w;
            s[12]+= qv*k3v.x;  s[13]+= qv*k3v.y;  s[14]+= qv*k3v.z;  s[15]+= qv*k3v.w;
        }
        // ---- online softmax ----
        float tmax = s[0];
        #pragma unroll
        for (int i=1;i<16;i++) tmax = fmaxf(tmax, s[i]);
        tmax = fmaxf(tmax, __shfl_xor_sync(0xffffffffu, tmax, 1));
        tmax = fmaxf(tmax, __shfl_xor_sync(0xffffffffu, tmax, 2));
        float m_old = row_m[srow];
        float m_new = fmaxf(m_old, tmax);
        float tsum = 0.f;
        #pragma unroll
        for (int i=0;i<16;i++){ s[i] = __expf(s[i]-m_new); tsum += s[i]; }
        tsum += __shfl_xor_sync(0xffffffffu, tsum, 1);
        tsum += __shfl_xor_sync(0xffffffffu, tsum, 2);
        #pragma unroll
        for (int i=0;i<16;i++) Ss[srow*65 + sjb + i] = s[i];
        if ((l&3)==0){
            float sc = __expf(m_old - m_new);
            row_sc[srow] = sc;
            row_l[srow]  = row_l[srow]*sc + tsum;
            row_m[srow]  = m_new;
        }
        __syncthreads();

        // ---- O update: acc[u][ci] = sum_j P[row][j] * V[ch][j] ----
        float scl[4];
        #pragma unroll
        for (int u=0;u<4;u++) scl[u] = row_sc[org+u];
        #pragma unroll
        for (int u=0;u<4;u++)
            #pragma unroll
            for (int c=0;c<16;c++) acc[u][c] *= scl[u];

        #pragma unroll
        for (int j4=0;j4<16;j4++){
            float p[4][4];
            #pragma unroll
            for (int u=0;u<4;u++)
                #pragma unroll
                for (int jv=0;jv<4;jv++) p[u][jv] = Ss[(org+u)*65 + (j4<<2) + jv];
            #pragma unroll
            for (int ci=0;ci<16;ci++){
                float4 vv = *(const float4*)&Vs[(occ+ci)*64 + (j4<<2)];
                #pragma unroll
                for (int u=0;u<4;u++){
                    acc[u][ci] += p[u][0]*vv.x;
                    acc[u][ci] += p[u][1]*vv.y;
                    acc[u][ci] += p[u][2]*vv.z;
                    acc[u][ci] += p[u][3]*vv.w;
                }
            }
        }
    }

    // ---- epilogue: normalize, residual, write y, BN partials ----
    float rl[4];
    #pragma unroll
    for (int u=0;u<4;u++) rl[u] = 1.f/row_l[org+u];
    const float gam = gamma[0];
    float psum[16], psq[16];
    #pragma unroll
    for (int ci=0;ci<16;ci++){ psum[ci]=0.f; psq[ci]=0.f; }
    #pragma unroll
    for (int u=0;u<4;u++){
        int n = i0 + org + u;
        #pragma unroll
        for (int ci=0;ci<16;ci++){
            int c = occ + ci;
            size_t off = ((size_t)b*CCH + c)*NPIX + n;
            float yv = gam*acc[u][ci]*rl[u] + x[off];
            g_y[off] = yv;
            psum[ci] += yv;
            psq[ci]  += yv*yv;
        }
    }
    int cta = blockIdx.y*NQT + blockIdx.x;
    #pragma unroll
    for (int ci=0;ci<16;ci++){
        float a = psum[ci], q = psq[ci];
        #pragma unroll
        for (int off=8; off>0; off>>=1){
            a += __shfl_xor_sync(0xffffffffu, a, off);
            q += __shfl_xor_sync(0xffffffffu, q, off);
        }
        if ((t&15)==0){
            g_psum[cta*CCH + occ + ci] = a;
            g_psq [cta*CCH + occ + ci] = q;
        }
    }
}

// ---------------------------------------------------------------------------
// Kernel C1: deterministic per-channel reduction of 512 CTA partials.
// ---------------------------------------------------------------------------
__global__ __launch_bounds__(256) void bnstat_kernel(
    const float* __restrict__ bnw, const float* __restrict__ bnb)
{
    __shared__ float ss[256], sq[256];
    const int c = blockIdx.x;
    const int t = threadIdx.x;
    float s = g_psum[t*CCH + c] + g_psum[(t+256)*CCH + c];
    float q = g_psq [t*CCH + c] + g_psq [(t+256)*CCH + c];
    ss[t]=s; sq[t]=q;
    __syncthreads();
    for (int off=128; off>0; off>>=1){
        if (t<off){ ss[t]+=ss[t+off]; sq[t]+=sq[t+off]; }
        __syncthreads();
    }
    if (t==0){
        const float inv = 1.f/32768.f;
        float mean = ss[0]*inv;
        float var  = sq[0]*inv - mean*mean;
        float rstd = rsqrtf(var + 1e-5f);
        float scale = bnw[c]*rstd;
        g_bn[c]       = scale;
        g_bn[CCH + c] = bnb[c] - mean*scale;
    }
}

// ---------------------------------------------------------------------------
// Kernel C2: BN apply + ReLU, float4 elementwise.
// ---------------------------------------------------------------------------
__global__ __launch_bounds__(256) void bnapply_kernel(float* __restrict__ out)
{
    int idx = blockIdx.x*256 + threadIdx.x;          // float4 index
    int c = (idx >> 10) & 255;                        // (idx*4 / 4096) % 256
    float scale = g_bn[c], shift = g_bn[CCH + c];
    float4 y = ((const float4*)g_y)[idx];
    float4 o;
    o.x = fmaxf(y.x*scale + shift, 0.f);
    o.y = fmaxf(y.y*scale + shift, 0.f);
    o.z = fmaxf(y.z*scale + shift, 0.f);
    o.w = fmaxf(y.w*scale + shift, 0.f);
    ((float4*)out)[idx] = o;
}

// ---------------------------------------------------------------------------
extern "C" void kernel_launch(void* const* d_in, const int* in_sizes, int n_in,
                              void* d_out, int out_size)
{
    const float* x     = (const float*)d_in[0];
    const float* wq    = (const float*)d_in[1];
    const float* bq    = (const float*)d_in[2];
    const float* wk    = (const float*)d_in[3];
    const float* bk    = (const float*)d_in[4];
    const float* wv    = (const float*)d_in[5];
    const float* bv    = (const float*)d_in[6];
    const float* gamma = (const float*)d_in[7];
    const float* bnw   = (const float*)d_in[8];
    const float* bnb   = (const float*)d_in[9];
    float* out = (float*)d_out;

    dim3 gA(NPIX/128, PROWS/64, BATCH);   // (32, 5, 8)
    proj_kernel<<<gA, 256>>>(x, wq, bq, wk, bk, wv, bv);

    const int attn_smem = 24832 * 4;      // 99328 B
    cudaFuncSetAttribute(attn_kernel, cudaFuncAttributeMaxDynamicSharedMemorySize, attn_smem);
    attn_kernel<<<dim3(NQT, BATCH), 256, attn_smem>>>(x, gamma);

    bnstat_kernel<<<CCH, 256>>>(bnw, bnb);

    bnapply_kernel<<<(BATCH*CCH*NPIX)/(256*4), 256>>>(out);
}

// round 4
// speedup vs baseline: 1.1192x; 1.1192x over previous
#include <cuda_runtime.h>

#define BATCH 8
#define CCH   256
#define DQK   32
#define NPIX  4096
#define PROWS 320
#define TQ    64
#define TK    64
#define NQT   (NPIX/TQ)            /* 64 */
#define NCTA_ATTN (BATCH*NQT)      /* 512 */

__device__ __align__(16) float g_proj[(size_t)BATCH*PROWS*NPIX]; /* rows: 0-31 q, 32-63 k, 64-319 v */
__device__ __align__(16) float g_y[(size_t)BATCH*CCH*NPIX];
__device__ __align__(16) float g_psum[NCTA_ATTN*CCH];
__device__ __align__(16) float g_psq[NCTA_ATTN*CCH];
__device__ __align__(16) float g_bn[2*CCH];

// ---- packed fp32x2 helpers (sm_100+ f32x2 pipe: 2 FMAs per issue slot) ----
__device__ __forceinline__ unsigned long long ffma2(unsigned long long a,
                                                    unsigned long long b,
                                                    unsigned long long c){
    unsigned long long d;
    asm("fma.rn.f32x2 %0, %1, %2, %3;" : "=l"(d) : "l"(a), "l"(b), "l"(c));
    return d;
}
__device__ __forceinline__ unsigned long long fmul2(unsigned long long a,
                                                    unsigned long long b){
    unsigned long long d;
    asm("mul.rn.f32x2 %0, %1, %2;" : "=l"(d) : "l"(a), "l"(b));
    return d;
}
__device__ __forceinline__ unsigned long long fpack2(float lo, float hi){
    unsigned long long d;
    asm("mov.b64 %0, {%1, %2};" : "=l"(d) : "f"(lo), "f"(hi));
    return d;
}
__device__ __forceinline__ float2 f2unpack(unsigned long long a){
    float x, y;
    asm("mov.b64 {%0, %1}, %2;" : "=f"(x), "=f"(y) : "l"(a));
    return make_float2(x, y);
}

// ---------------------------------------------------------------------------
// Kernel A: fused projection GEMM.  out[b][row][n] = W[row] . x[b][:][n] + bias
// ---------------------------------------------------------------------------
__global__ __launch_bounds__(256) void proj_kernel(
    const float* __restrict__ x,
    const float* __restrict__ wq, const float* __restrict__ bq,
    const float* __restrict__ wk, const float* __restrict__ bk,
    const float* __restrict__ wv, const float* __restrict__ bv)
{
    __shared__ float Wt[32*64];    // [kk][row]
    __shared__ float Xt[32*128];   // [kk][col]
    const int t  = threadIdx.x;
    const int nt = blockIdx.x;
    const int rt = blockIdx.y;
    const int b  = blockIdx.z;
    const int n0 = nt*128;
    const int rowbase = rt*64;
    const int cg = t & 31;
    const int rg = t >> 5;
    const int col = cg*4;
    const float* xb = x + (size_t)b*CCH*NPIX;

    float4 acc[8];
    #pragma unroll
    for (int i=0;i<8;i++) acc[i] = make_float4(0.f,0.f,0.f,0.f);

    for (int k0=0;k0<CCH;k0+=32){
        __syncthreads();
        #pragma unroll
        for (int i=0;i<2;i++){
            int idx = t*2+i;
            int r   = idx >> 3;
            int kc  = idx & 7;
            int grow = rowbase + r;
            const float* wsrc;
            int lrow;
            if (grow < 32)      { wsrc = wq; lrow = grow; }
            else if (grow < 64) { wsrc = wk; lrow = grow-32; }
            else                { wsrc = wv; lrow = grow-64; }
            float4 wv4 = *(const float4*)(wsrc + (size_t)lrow*CCH + k0 + kc*4);
            Wt[(kc*4+0)*64 + r] = wv4.x;
            Wt[(kc*4+1)*64 + r] = wv4.y;
            Wt[(kc*4+2)*64 + r] = wv4.z;
            Wt[(kc*4+3)*64 + r] = wv4.w;
        }
        #pragma unroll
        for (int i=0;i<4;i++){
            int idx = i*256 + t;
            int kk  = idx >> 5;
            int cc  = (idx & 31)*4;
            float4 xv = *(const float4*)(xb + (size_t)(k0+kk)*NPIX + n0 + cc);
            *(float4*)&Xt[kk*128 + cc] = xv;
        }
        __syncthreads();
        #pragma unroll
        for (int kk=0;kk<32;kk++){
            float4 xv = *(float4*)&Xt[kk*128 + col];
            float4 wa = *(float4*)&Wt[kk*64 + rg*8];
            float4 wb = *(float4*)&Wt[kk*64 + rg*8 + 4];
            float wr[8] = {wa.x,wa.y,wa.z,wa.w,wb.x,wb.y,wb.z,wb.w};
            #pragma unroll
            for (int i=0;i<8;i++){
                acc[i].x += wr[i]*xv.x;
                acc[i].y += wr[i]*xv.y;
                acc[i].z += wr[i]*xv.z;
                acc[i].w += wr[i]*xv.w;
            }
        }
    }
    #pragma unroll
    for (int i=0;i<8;i++){
        int grow = rowbase + rg*8 + i;
        float bias;
        if (grow < 32)      bias = bq[grow];
        else if (grow < 64) bias = bk[grow-32];
        else                bias = bv[grow-64];
        float4 o = acc[i];
        o.x += bias; o.y += bias; o.z += bias; o.w += bias;
        *(float4*)(g_proj + ((size_t)b*PROWS + grow)*NPIX + n0 + col) = o;
    }
}

// ---------------------------------------------------------------------------
// Kernel B: flash attention with packed f32x2 FMA everywhere.
// 512 threads, grid (64, 8).  smem ~100KB.
// Layouts: Qs/Ks row-major [64][34] (d contiguous, pad 34 for banks),
//          Vs [256][64] c-major, Ss [64][65].
// ---------------------------------------------------------------------------
__global__ __launch_bounds__(512) void attn_kernel(
    const float* __restrict__ x, const float* __restrict__ gamma)
{
    extern __shared__ float sm[];
    float* Qs     = sm;                       // [64][34]
    float* Ks     = sm + 64*34;               // [64][34]
    float* Vs     = sm + 2*64*34;             // [256][64]
    float* Ss     = Vs + 256*64;              // [64][65]
    float* row_m  = Ss + 64*65;               // [64]
    float* row_l  = row_m + 64;               // [64]
    float* row_sc = row_l + 64;               // [64]

    const int t  = threadIdx.x;
    const int b  = blockIdx.y;
    const int i0 = blockIdx.x * TQ;
    const float* qg = g_proj + (size_t)b*PROWS*NPIX;
    const float* kg = qg + (size_t)32*NPIX;
    const float* vg = qg + (size_t)64*NPIX;

    // load Q tile: Qs[r][d], d contiguous
    #pragma unroll
    for (int i=0;i<4;i++){
        int idx = i*512 + t;
        int d = idx >> 6, r = idx & 63;
        Qs[r*34 + d] = qg[(size_t)d*NPIX + i0 + r];
    }
    if (t < 64){ row_m[t] = -1e30f; row_l[t] = 0.f; }

    const int w  = t >> 5;          // warp 0..15
    const int l  = t & 31;
    const int hw = l >> 4;          // half-warp
    const int jb = l & 15;
    const int r0q = w*4 + hw*2;     // QK rows: r0q, r0q+1
    const int lo  = l;              // O rows: lo, lo+32
    const int cb  = w*16;           // O channels: cb..cb+15

    unsigned long long pacc[2][16]; // f32x2 partial pairs over j
    #pragma unroll
    for (int u=0;u<2;u++)
        #pragma unroll
        for (int ci=0;ci<16;ci++) pacc[u][ci] = 0ULL;

    for (int j0=0;j0<NPIX;j0+=TK){
        __syncthreads();            // prev tile's O reads done
        // K tile: Ks[j][d]
        #pragma unroll
        for (int i=0;i<4;i++){
            int idx = i*512 + t;
            int d = idx >> 6, j = idx & 63;
            Ks[j*34 + d] = kg[(size_t)d*NPIX + j0 + j];
        }
        // V tile: Vs[c][j]
        #pragma unroll
        for (int i=0;i<8;i++){
            int idx = i*512 + t;
            int c = idx >> 4, rc = (idx & 15) << 2;
            *(float4*)&Vs[c*64 + rc] = *(const float4*)(vg + (size_t)c*NPIX + j0 + rc);
        }
        __syncthreads();

        // ---- QK: 2 rows x 4 j per thread, packed over d ----
        unsigned long long s2[2][4];
        #pragma unroll
        for (int u=0;u<2;u++)
            #pragma unroll
            for (int jv=0;jv<4;jv++) s2[u][jv] = 0ULL;
        #pragma unroll
        for (int dp=0;dp<16;dp++){
            unsigned long long q0 = *(const unsigned long long*)&Qs[ r0q   *34 + 2*dp];
            unsigned long long q1 = *(const unsigned long long*)&Qs[(r0q+1)*34 + 2*dp];
            #pragma unroll
            for (int jv=0;jv<4;jv++){
                unsigned long long kk = *(const unsigned long long*)&Ks[(jb+16*jv)*34 + 2*dp];
                s2[0][jv] = ffma2(q0, kk, s2[0][jv]);
                s2[1][jv] = ffma2(q1, kk, s2[1][jv]);
            }
        }
        // ---- online softmax (row = half-warp local) ----
        #pragma unroll
        for (int u=0;u<2;u++){
            const int r = r0q + u;
            float s[4];
            #pragma unroll
            for (int jv=0;jv<4;jv++){
                float2 f = f2unpack(s2[u][jv]);
                s[jv] = f.x + f.y;
            }
            float tm = fmaxf(fmaxf(s[0],s[1]), fmaxf(s[2],s[3]));
            tm = fmaxf(tm, __shfl_xor_sync(0xffffffffu, tm, 1));
            tm = fmaxf(tm, __shfl_xor_sync(0xffffffffu, tm, 2));
            tm = fmaxf(tm, __shfl_xor_sync(0xffffffffu, tm, 4));
            tm = fmaxf(tm, __shfl_xor_sync(0xffffffffu, tm, 8));
            float m_old = row_m[r];
            float m_new = fmaxf(m_old, tm);
            float ts = 0.f;
            #pragma unroll
            for (int jv=0;jv<4;jv++){
                float p = __expf(s[jv] - m_new);
                Ss[r*65 + jb + 16*jv] = p;
                ts += p;
            }
            ts += __shfl_xor_sync(0xffffffffu, ts, 1);
            ts += __shfl_xor_sync(0xffffffffu, ts, 2);
            ts += __shfl_xor_sync(0xffffffffu, ts, 4);
            ts += __shfl_xor_sync(0xffffffffu, ts, 8);
            float sc = __expf(m_old - m_new);
            if (jb == 0){
                row_sc[r] = sc;
                row_l[r]  = row_l[r]*sc + ts;
                row_m[r]  = m_new;
            }
        }
        __syncthreads();

        // ---- O update: rescale then accumulate, packed over j-pairs ----
        #pragma unroll
        for (int u=0;u<2;u++){
            float sc = row_sc[lo + 32*u];
            unsigned long long sc2 = fpack2(sc, sc);
            #pragma unroll
            for (int ci=0;ci<16;ci++) pacc[u][ci] = fmul2(pacc[u][ci], sc2);
        }
        #pragma unroll
        for (int j4=0;j4<16;j4++){
            unsigned long long pp[2][2];
            #pragma unroll
            for (int u=0;u<2;u++){
                const float* srow = &Ss[(lo+32*u)*65 + j4*4];
                pp[u][0] = fpack2(srow[0], srow[1]);
                pp[u][1] = fpack2(srow[2], srow[3]);
            }
            #pragma unroll
            for (int ci=0;ci<16;ci++){
                const ulonglong2 vv = *(const ulonglong2*)&Vs[(cb+ci)*64 + (j4<<2)];
                pacc[0][ci] = ffma2(pp[0][0], vv.x, pacc[0][ci]);
                pacc[0][ci] = ffma2(pp[0][1], vv.y, pacc[0][ci]);
                pacc[1][ci] = ffma2(pp[1][0], vv.x, pacc[1][ci]);
                pacc[1][ci] = ffma2(pp[1][1], vv.y, pacc[1][ci]);
            }
        }
    }

    // ---- epilogue: normalize, residual, write y, BN partials ----
    float rl[2];
    #pragma unroll
    for (int u=0;u<2;u++) rl[u] = 1.f/row_l[lo + 32*u];
    const float gam = gamma[0];
    float ps[16], pq[16];
    #pragma unroll
    for (int ci=0;ci<16;ci++){ ps[ci]=0.f; pq[ci]=0.f; }
    #pragma unroll
    for (int u=0;u<2;u++){
        int n = i0 + lo + 32*u;
        #pragma unroll
        for (int ci=0;ci<16;ci++){
            int c = cb + ci;
            size_t off = ((size_t)b*CCH + c)*NPIX + n;
            float2 f = f2unpack(pacc[u][ci]);
            float yv = gam*(f.x + f.y)*rl[u] + x[off];
            g_y[off] = yv;
            ps[ci] += yv;
            pq[ci] += yv*yv;
        }
    }
    const int cta = b*NQT + blockIdx.x;
    #pragma unroll
    for (int ci=0;ci<16;ci++){
        float a = ps[ci], q = pq[ci];
        #pragma unroll
        for (int off=16; off>0; off>>=1){
            a += __shfl_xor_sync(0xffffffffu, a, off);
            q += __shfl_xor_sync(0xffffffffu, q, off);
        }
        if (l == 0){
            g_psum[cta*CCH + cb + ci] = a;
            g_psq [cta*CCH + cb + ci] = q;
        }
    }
}

// ---------------------------------------------------------------------------
// Kernel C1: deterministic per-channel reduction of 512 CTA partials.
// ---------------------------------------------------------------------------
__global__ __launch_bounds__(256) void bnstat_kernel(
    const float* __restrict__ bnw, const float* __restrict__ bnb)
{
    __shared__ float ss[256], sq[256];
    const int c = blockIdx.x;
    const int t = threadIdx.x;
    float s = g_psum[t*CCH + c] + g_psum[(t+256)*CCH + c];
    float q = g_psq [t*CCH + c] + g_psq [(t+256)*CCH + c];
    ss[t]=s; sq[t]=q;
    __syncthreads();
    for (int off=128; off>0; off>>=1){
        if (t<off){ ss[t]+=ss[t+off]; sq[t]+=sq[t+off]; }
        __syncthreads();
    }
    if (t==0){
        const float inv = 1.f/32768.f;
        float mean = ss[0]*inv;
        float var  = sq[0]*inv - mean*mean;
        float rstd = rsqrtf(var + 1e-5f);
        float scale = bnw[c]*rstd;
        g_bn[c]       = scale;
        g_bn[CCH + c] = bnb[c] - mean*scale;
    }
}

// ---------------------------------------------------------------------------
// Kernel C2: BN apply + ReLU, float4 elementwise.
// ---------------------------------------------------------------------------
__global__ __launch_bounds__(256) void bnapply_kernel(float* __restrict__ out)
{
    int idx = blockIdx.x*256 + threadIdx.x;
    int c = (idx >> 10) & 255;
    float scale = g_bn[c], shift = g_bn[CCH + c];
    float4 y = ((const float4*)g_y)[idx];
    float4 o;
    o.x = fmaxf(y.x*scale + shift, 0.f);
    o.y = fmaxf(y.y*scale + shift, 0.f);
    o.z = fmaxf(y.z*scale + shift, 0.f);
    o.w = fmaxf(y.w*scale + shift, 0.f);
    ((float4*)out)[idx] = o;
}

// ---------------------------------------------------------------------------
extern "C" void kernel_launch(void* const* d_in, const int* in_sizes, int n_in,
                              void* d_out, int out_size)
{
    const float* x     = (const float*)d_in[0];
    const float* wq    = (const float*)d_in[1];
    const float* bq    = (const float*)d_in[2];
    const float* wk    = (const float*)d_in[3];
    const float* bk    = (const float*)d_in[4];
    const float* wv    = (const float*)d_in[5];
    const float* bv    = (const float*)d_in[6];
    const float* gamma = (const float*)d_in[7];
    const float* bnw   = (const float*)d_in[8];
    const float* bnb   = (const float*)d_in[9];
    float* out = (float*)d_out;

    dim3 gA(NPIX/128, PROWS/64, BATCH);   // (32, 5, 8)
    proj_kernel<<<gA, 256>>>(x, wq, bq, wk, bk, wv, bv);

    const int attn_smem = (64*34*2 + 256*64 + 64*65 + 192) * 4;   // 100,352 B
    cudaFuncSetAttribute(attn_kernel, cudaFuncAttributeMaxDynamicSharedMemorySize, attn_smem);
    attn_kernel<<<dim3(NQT, BATCH), 512, attn_smem>>>(x, gamma);

    bnstat_kernel<<<CCH, 256>>>(bnw, bnb);

    bnapply_kernel<<<(BATCH*CCH*NPIX)/(256*4), 256>>>(out);
}

// round 6
// speedup vs baseline: 1.1793x; 1.0537x over previous
#include <cuda_runtime.h>

#define BATCH 8
#define CCH   256
#define DQK   32
#define NPIX  4096
#define PROWS 320
#define TQ    64
#define TK    64
#define NQT   (NPIX/TQ)            /* 64 */
#define NCTA_ATTN (BATCH*NQT)      /* 512 */

__device__ __align__(16) float g_proj[(size_t)BATCH*PROWS*NPIX]; /* rows: 0-31 q, 32-63 k, 64-319 v */
__device__ __align__(16) float g_y[(size_t)BATCH*CCH*NPIX];
__device__ __align__(16) float g_psum[NCTA_ATTN*CCH];
__device__ __align__(16) float g_psq[NCTA_ATTN*CCH];
__device__ __align__(16) float g_bn[2*CCH];

// ---- packed fp32x2 helpers (sm_100+ f32x2 pipe: 2 FMAs per issue slot) ----
__device__ __forceinline__ unsigned long long ffma2(unsigned long long a,
                                                    unsigned long long b,
                                                    unsigned long long c){
    unsigned long long d;
    asm("fma.rn.f32x2 %0, %1, %2, %3;" : "=l"(d) : "l"(a), "l"(b), "l"(c));
    return d;
}
__device__ __forceinline__ unsigned long long fmul2(unsigned long long a,
                                                    unsigned long long b){
    unsigned long long d;
    asm("mul.rn.f32x2 %0, %1, %2;" : "=l"(d) : "l"(a), "l"(b));
    return d;
}
__device__ __forceinline__ unsigned long long fpack2(float lo, float hi){
    unsigned long long d;
    asm("mov.b64 %0, {%1, %2};" : "=l"(d) : "f"(lo), "f"(hi));
    return d;
}
__device__ __forceinline__ float2 f2unpack(unsigned long long a){
    float x, y;
    asm("mov.b64 {%0, %1}, %2;" : "=f"(x), "=f"(y) : "l"(a));
    return make_float2(x, y);
}

// ---------------------------------------------------------------------------
// Kernel A: fused projection GEMM.  out[b][row][n] = W[row] . x[b][:][n] + bias
// ---------------------------------------------------------------------------
__global__ __launch_bounds__(256) void proj_kernel(
    const float* __restrict__ x,
    const float* __restrict__ wq, const float* __restrict__ bq,
    const float* __restrict__ wk, const float* __restrict__ bk,
    const float* __restrict__ wv, const float* __restrict__ bv)
{
    __shared__ float Wt[32*64];    // [kk][row]
    __shared__ float Xt[32*128];   // [kk][col]
    const int t  = threadIdx.x;
    const int nt = blockIdx.x;
    const int rt = blockIdx.y;
    const int b  = blockIdx.z;
    const int n0 = nt*128;
    const int rowbase = rt*64;
    const int cg = t & 31;
    const int rg = t >> 5;
    const int col = cg*4;
    const float* xb = x + (size_t)b*CCH*NPIX;

    float4 acc[8];
    #pragma unroll
    for (int i=0;i<8;i++) acc[i] = make_float4(0.f,0.f,0.f,0.f);

    for (int k0=0;k0<CCH;k0+=32){
        __syncthreads();
        #pragma unroll
        for (int i=0;i<2;i++){
            int idx = t*2+i;
            int r   = idx >> 3;
            int kc  = idx & 7;
            int grow = rowbase + r;
            const float* wsrc;
            int lrow;
            if (grow < 32)      { wsrc = wq; lrow = grow; }
            else if (grow < 64) { wsrc = wk; lrow = grow-32; }
            else                { wsrc = wv; lrow = grow-64; }
            float4 wv4 = *(const float4*)(wsrc + (size_t)lrow*CCH + k0 + kc*4);
            Wt[(kc*4+0)*64 + r] = wv4.x;
            Wt[(kc*4+1)*64 + r] = wv4.y;
            Wt[(kc*4+2)*64 + r] = wv4.z;
            Wt[(kc*4+3)*64 + r] = wv4.w;
        }
        #pragma unroll
        for (int i=0;i<4;i++){
            int idx = i*256 + t;
            int kk  = idx >> 5;
            int cc  = (idx & 31)*4;
            float4 xv = *(const float4*)(xb + (size_t)(k0+kk)*NPIX + n0 + cc);
            *(float4*)&Xt[kk*128 + cc] = xv;
        }
        __syncthreads();
        #pragma unroll
        for (int kk=0;kk<32;kk++){
            float4 xv = *(float4*)&Xt[kk*128 + col];
            float4 wa = *(float4*)&Wt[kk*64 + rg*8];
            float4 wb = *(float4*)&Wt[kk*64 + rg*8 + 4];
            float wr[8] = {wa.x,wa.y,wa.z,wa.w,wb.x,wb.y,wb.z,wb.w};
            #pragma unroll
            for (int i=0;i<8;i++){
                acc[i].x += wr[i]*xv.x;
                acc[i].y += wr[i]*xv.y;
                acc[i].z += wr[i]*xv.z;
                acc[i].w += wr[i]*xv.w;
            }
        }
    }
    #pragma unroll
    for (int i=0;i<8;i++){
        int grow = rowbase + rg*8 + i;
        float bias;
        if (grow < 32)      bias = bq[grow];
        else if (grow < 64) bias = bk[grow-32];
        else                bias = bv[grow-64];
        float4 o = acc[i];
        o.x += bias; o.y += bias; o.z += bias; o.w += bias;
        *(float4*)(g_proj + ((size_t)b*PROWS + grow)*NPIX + n0 + col) = o;
    }
}

// ---------------------------------------------------------------------------
// Kernel B: flash attention with packed f32x2 FMA everywhere.
// 512 threads, grid (64, 8).  smem ~100KB.
// Layouts: Qs/Ks row-major [64][34] (d contiguous, pad 34 for banks),
//          Vs [256][64] c-major, Ss [64][65].
// ---------------------------------------------------------------------------
__global__ __launch_bounds__(512) void attn_kernel(
    const float* __restrict__ x, const float* __restrict__ gamma)
{
    extern __shared__ float sm[];
    float* Qs     = sm;                       // [64][34]
    float* Ks     = sm + 64*34;               // [64][34]
    float* Vs     = sm + 2*64*34;             // [256][64]
    float* Ss     = Vs + 256*64;              // [64][65]
    float* row_m  = Ss + 64*65;               // [64]
    float* row_l  = row_m + 64;               // [64]
    float* row_sc = row_l + 64;               // [64]

    const int t  = threadIdx.x;
    const int b  = blockIdx.y;
    const int i0 = blockIdx.x * TQ;
    const float* qg = g_proj + (size_t)b*PROWS*NPIX;
    const float* kg = qg + (size_t)32*NPIX;
    const float* vg = qg + (size_t)64*NPIX;

    // load Q tile: Qs[r][d], d contiguous
    #pragma unroll
    for (int i=0;i<4;i++){
        int idx = i*512 + t;
        int d = idx >> 6, r = idx & 63;
        Qs[r*34 + d] = qg[(size_t)d*NPIX + i0 + r];
    }
    if (t < 64){ row_m[t] = -1e30f; row_l[t] = 0.f; }

    const int w  = t >> 5;          // warp 0..15
    const int l  = t & 31;
    const int hw = l >> 4;          // half-warp
    const int jb = l & 15;
    const int r0q = w*4 + hw*2;     // QK rows: r0q, r0q+1
    const int lo  = l;              // O rows: lo, lo+32
    const int cb  = w*16;           // O channels: cb..cb+15

    unsigned long long pacc[2][16]; // f32x2 partial pairs over j
    #pragma unroll
    for (int u=0;u<2;u++)
        #pragma unroll
        for (int ci=0;ci<16;ci++) pacc[u][ci] = 0ULL;

    for (int j0=0;j0<NPIX;j0+=TK){
        __syncthreads();            // prev tile's O reads done
        // K tile: Ks[j][d]
        #pragma unroll
        for (int i=0;i<4;i++){
            int idx = i*512 + t;
            int d = idx >> 6, j = idx & 63;
            Ks[j*34 + d] = kg[(size_t)d*NPIX + j0 + j];
        }
        // V tile: Vs[c][j]
        #pragma unroll
        for (int i=0;i<8;i++){
            int idx = i*512 + t;
            int c = idx >> 4, rc = (idx & 15) << 2;
            *(float4*)&Vs[c*64 + rc] = *(const float4*)(vg + (size_t)c*NPIX + j0 + rc);
        }
        __syncthreads();

        // ---- QK: 2 rows x 4 j per thread, packed over d ----
        unsigned long long s2[2][4];
        #pragma unroll
        for (int u=0;u<2;u++)
            #pragma unroll
            for (int jv=0;jv<4;jv++) s2[u][jv] = 0ULL;
        #pragma unroll
        for (int dp=0;dp<16;dp++){
            unsigned long long q0 = *(const unsigned long long*)&Qs[ r0q   *34 + 2*dp];
            unsigned long long q1 = *(const unsigned long long*)&Qs[(r0q+1)*34 + 2*dp];
            #pragma unroll
            for (int jv=0;jv<4;jv++){
                unsigned long long kk = *(const unsigned long long*)&Ks[(jb+16*jv)*34 + 2*dp];
                s2[0][jv] = ffma2(q0, kk, s2[0][jv]);
                s2[1][jv] = ffma2(q1, kk, s2[1][jv]);
            }
        }
        // ---- online softmax (row = half-warp local) ----
        #pragma unroll
        for (int u=0;u<2;u++){
            const int r = r0q + u;
            float s[4];
            #pragma unroll
            for (int jv=0;jv<4;jv++){
                float2 f = f2unpack(s2[u][jv]);
                s[jv] = f.x + f.y;
            }
            float tm = fmaxf(fmaxf(s[0],s[1]), fmaxf(s[2],s[3]));
            tm = fmaxf(tm, __shfl_xor_sync(0xffffffffu, tm, 1));
            tm = fmaxf(tm, __shfl_xor_sync(0xffffffffu, tm, 2));
            tm = fmaxf(tm, __shfl_xor_sync(0xffffffffu, tm, 4));
            tm = fmaxf(tm, __shfl_xor_sync(0xffffffffu, tm, 8));
            float m_old = row_m[r];
            float m_new = fmaxf(m_old, tm);
            float ts = 0.f;
            #pragma unroll
            for (int jv=0;jv<4;jv++){
                float p = __expf(s[jv] - m_new);
                Ss[r*65 + jb + 16*jv] = p;
                ts += p;
            }
            ts += __shfl_xor_sync(0xffffffffu, ts, 1);
            ts += __shfl_xor_sync(0xffffffffu, ts, 2);
            ts += __shfl_xor_sync(0xffffffffu, ts, 4);
            ts += __shfl_xor_sync(0xffffffffu, ts, 8);
            float sc = __expf(m_old - m_new);
            if (jb == 0){
                row_sc[r] = sc;
                row_l[r]  = row_l[r]*sc + ts;
                row_m[r]  = m_new;
            }
        }
        __syncthreads();

        // ---- O update: rescale then accumulate, packed over j-pairs ----
        #pragma unroll
        for (int u=0;u<2;u++){
            float sc = row_sc[lo + 32*u];
            unsigned long long sc2 = fpack2(sc, sc);
            #pragma unroll
            for (int ci=0;ci<16;ci++) pacc[u][ci] = fmul2(pacc[u][ci], sc2);
        }
        #pragma unroll
        for (int j4=0;j4<16;j4++){
            unsigned long long pp[2][2];
            #pragma unroll
            for (int u=0;u<2;u++){
                const float* srow = &Ss[(lo+32*u)*65 + j4*4];
                pp[u][0] = fpack2(srow[0], srow[1]);
                pp[u][1] = fpack2(srow[2], srow[3]);
            }
            #pragma unroll
            for (int ci=0;ci<16;ci++){
                const ulonglong2 vv = *(const ulonglong2*)&Vs[(cb+ci)*64 + (j4<<2)];
                pacc[0][ci] = ffma2(pp[0][0], vv.x, pacc[0][ci]);
                pacc[0][ci] = ffma2(pp[0][1], vv.y, pacc[0][ci]);
                pacc[1][ci] = ffma2(pp[1][0], vv.x, pacc[1][ci]);
                pacc[1][ci] = ffma2(pp[1][1], vv.y, pacc[1][ci]);
            }
        }
    }

    // ---- epilogue: normalize, residual, write y, BN partials ----
    float rl[2];
    #pragma unroll
    for (int u=0;u<2;u++) rl[u] = 1.f/row_l[lo + 32*u];
    const float gam = gamma[0];
    float ps[16], pq[16];
    #pragma unroll
    for (int ci=0;ci<16;ci++){ ps[ci]=0.f; pq[ci]=0.f; }
    #pragma unroll
    for (int u=0;u<2;u++){
        int n = i0 + lo + 32*u;
        #pragma unroll
        for (int ci=0;ci<16;ci++){
            int c = cb + ci;
            size_t off = ((size_t)b*CCH + c)*NPIX + n;
            float2 f = f2unpack(pacc[u][ci]);
            float yv = gam*(f.x + f.y)*rl[u] + x[off];
            g_y[off] = yv;
            ps[ci] += yv;
            pq[ci] += yv*yv;
        }
    }
    const int cta = b*NQT + blockIdx.x;
    #pragma unroll
    for (int ci=0;ci<16;ci++){
        float a = ps[ci], q = pq[ci];
        #pragma unroll
        for (int off=16; off>0; off>>=1){
            a += __shfl_xor_sync(0xffffffffu, a, off);
            q += __shfl_xor_sync(0xffffffffu, q, off);
        }
        if (l == 0){
            g_psum[cta*CCH + cb + ci] = a;
            g_psq [cta*CCH + cb + ci] = q;
        }
    }
}

// ---------------------------------------------------------------------------
// Kernel C1: deterministic per-channel reduction of 512 CTA partials.
// ---------------------------------------------------------------------------
__global__ __launch_bounds__(256) void bnstat_kernel(
    const float* __restrict__ bnw, const float* __restrict__ bnb)
{
    __shared__ float ss[256], sq[256];
    const int c = blockIdx.x;
    const int t = threadIdx.x;
    float s = g_psum[t*CCH + c] + g_psum[(t+256)*CCH + c];
    float q = g_psq [t*CCH + c] + g_psq [(t+256)*CCH + c];
    ss[t]=s; sq[t]=q;
    __syncthreads();
    for (int off=128; off>0; off>>=1){
        if (t<off){ ss[t]+=ss[t+off]; sq[t]+=sq[t+off]; }
        __syncthreads();
    }
    if (t==0){
        const float inv = 1.f/32768.f;
        float mean = ss[0]*inv;
        float var  = sq[0]*inv - mean*mean;
        float rstd = rsqrtf(var + 1e-5f);
        float scale = bnw[c]*rstd;
        g_bn[c]       = scale;
        g_bn[CCH + c] = bnb[c] - mean*scale;
    }
}

// ---------------------------------------------------------------------------
// Kernel C2: BN apply + ReLU, float4 elementwise.
// ---------------------------------------------------------------------------
__global__ __launch_bounds__(256) void bnapply_kernel(float* __restrict__ out)
{
    int idx = blockIdx.x*256 + threadIdx.x;
    int c = (idx >> 10) & 255;
    float scale = g_bn[c], shift = g_bn[CCH + c];
    float4 y = ((const float4*)g_y)[idx];
    float4 o;
    o.x = fmaxf(y.x*scale + shift, 0.f);
    o.y = fmaxf(y.y*scale + shift, 0.f);
    o.z = fmaxf(y.z*scale + shift, 0.f);
    o.w = fmaxf(y.w*scale + shift, 0.f);
    ((float4*)out)[idx] = o;
}

// ---------------------------------------------------------------------------
extern "C" void kernel_launch(void* const* d_in, const int* in_sizes, int n_in,
                              void* d_out, int out_size)
{
    const float* x     = (const float*)d_in[0];
    const float* wq    = (const float*)d_in[1];
    const float* bq    = (const float*)d_in[2];
    const float* wk    = (const float*)d_in[3];
    const float* bk    = (const float*)d_in[4];
    const float* wv    = (const float*)d_in[5];
    const float* bv    = (const float*)d_in[6];
    const float* gamma = (const float*)d_in[7];
    const float* bnw   = (const float*)d_in[8];
    const float* bnb   = (const float*)d_in[9];
    float* out = (float*)d_out;

    dim3 gA(NPIX/128, PROWS/64, BATCH);   // (32, 5, 8)
    proj_kernel<<<gA, 256>>>(x, wq, bq, wk, bk, wv, bv);

    const int attn_smem = (64*34*2 + 256*64 + 64*65 + 192) * 4;   // 100,352 B
    cudaFuncSetAttribute(attn_kernel, cudaFuncAttributeMaxDynamicSharedMemorySize, attn_smem);
    attn_kernel<<<dim3(NQT, BATCH), 512, attn_smem>>>(x, gamma);

    bnstat_kernel<<<CCH, 256>>>(bnw, bnb);

    bnapply_kernel<<<(BATCH*CCH*NPIX)/(256*4), 256>>>(out);
}

// round 7
// speedup vs baseline: 3.0479x; 2.5846x over previous
#include <cuda_runtime.h>
#include <cstdint>

#define BATCH 8
#define CCH   256
#define NPIX  4096
#define PROWS 320
#define TQ    64
#define TK    64
#define NQT   (NPIX/TQ)
#define NCTA_ATTN (BATCH*NQT)

__device__ __align__(16) float g_proj[(size_t)BATCH*PROWS*NPIX];
__device__ __align__(16) float g_y[(size_t)BATCH*CCH*NPIX];
__device__ __align__(16) float g_psum[NCTA_ATTN*CCH];
__device__ __align__(16) float g_psq[NCTA_ATTN*CCH];
__device__ __align__(16) float g_bn[2*CCH];

__device__ __forceinline__ uint32_t f2tf(float f){
    uint32_t r; asm("cvt.rna.tf32.f32 %0, %1;" : "=r"(r) : "f"(f)); return r;
}
__device__ __forceinline__ void mma_tf32(float* d, const uint32_t* a, uint32_t b0, uint32_t b1){
    asm("mma.sync.aligned.m16n8k8.row.col.f32.tf32.tf32.f32 "
        "{%0,%1,%2,%3},{%4,%5,%6,%7},{%8,%9},{%0,%1,%2,%3};"
        : "+f"(d[0]), "+f"(d[1]), "+f"(d[2]), "+f"(d[3])
        : "r"(a[0]), "r"(a[1]), "r"(a[2]), "r"(a[3]), "r"(b0), "r"(b1));
}

// ---------------- Kernel A: projection GEMM (V rows pre-rounded to tf32) ----
__global__ __launch_bounds__(256) void proj_kernel(
    const float* __restrict__ x,
    const float* __restrict__ wq, const float* __restrict__ bq,
    const float* __restrict__ wk, const float* __restrict__ bk,
    const float* __restrict__ wv, const float* __restrict__ bv)
{
    __shared__ float Wt[32*64];
    __shared__ float Xt[32*128];
    const int t  = threadIdx.x;
    const int n0 = blockIdx.x*128;
    const int rowbase = blockIdx.y*64;
    const int b  = blockIdx.z;
    const int cg = t & 31, rg = t >> 5;
    const int col = cg*4;
    const float* xb = x + (size_t)b*CCH*NPIX;

    float4 acc[8];
    #pragma unroll
    for (int i=0;i<8;i++) acc[i] = make_float4(0.f,0.f,0.f,0.f);

    for (int k0=0;k0<CCH;k0+=32){
        __syncthreads();
        #pragma unroll
        for (int i=0;i<2;i++){
            int idx = t*2+i;
            int r = idx >> 3, kc = idx & 7;
            int grow = rowbase + r;
            const float* wsrc; int lrow;
            if (grow < 32)      { wsrc = wq; lrow = grow; }
            else if (grow < 64) { wsrc = wk; lrow = grow-32; }
            else                { wsrc = wv; lrow = grow-64; }
            float4 wv4 = *(const float4*)(wsrc + (size_t)lrow*CCH + k0 + kc*4);
            Wt[(kc*4+0)*64 + r] = wv4.x;
            Wt[(kc*4+1)*64 + r] = wv4.y;
            Wt[(kc*4+2)*64 + r] = wv4.z;
            Wt[(kc*4+3)*64 + r] = wv4.w;
        }
        #pragma unroll
        for (int i=0;i<4;i++){
            int idx = i*256 + t;
            int kk = idx >> 5, cc = (idx & 31)*4;
            *(float4*)&Xt[kk*128 + cc] = *(const float4*)(xb + (size_t)(k0+kk)*NPIX + n0 + cc);
        }
        __syncthreads();
        #pragma unroll
        for (int kk=0;kk<32;kk++){
            float4 xv = *(float4*)&Xt[kk*128 + col];
            float4 wa = *(float4*)&Wt[kk*64 + rg*8];
            float4 wb = *(float4*)&Wt[kk*64 + rg*8 + 4];
            float wr[8] = {wa.x,wa.y,wa.z,wa.w,wb.x,wb.y,wb.z,wb.w};
            #pragma unroll
            for (int i=0;i<8;i++){
                acc[i].x += wr[i]*xv.x;  acc[i].y += wr[i]*xv.y;
                acc[i].z += wr[i]*xv.z;  acc[i].w += wr[i]*xv.w;
            }
        }
    }
    #pragma unroll
    for (int i=0;i<8;i++){
        int grow = rowbase + rg*8 + i;
        float bias;
        if (grow < 32)      bias = bq[grow];
        else if (grow < 64) bias = bk[grow-32];
        else                bias = bv[grow-64];
        float4 o = acc[i];
        o.x += bias; o.y += bias; o.z += bias; o.w += bias;
        if (grow >= 64){
            o.x = __uint_as_float(f2tf(o.x));  o.y = __uint_as_float(f2tf(o.y));
            o.z = __uint_as_float(f2tf(o.z));  o.w = __uint_as_float(f2tf(o.w));
        }
        *(float4*)(g_proj + ((size_t)b*PROWS + grow)*NPIX + n0 + col) = o;
    }
}

// ---------------- Kernel B: tf32 tensor-core flash attention -----------------
// 256 thr (8 warps), grid (64,8), ~107KB smem, 2 CTAs/SM.
// QK: split-tf32 (3 chains).  PV: tf32 computing O^T[c][i] = V[c][j]*P[i][j].
__global__ __launch_bounds__(256,2) void attn_kernel(
    const float* __restrict__ x, const float* __restrict__ gamma)
{
    extern __shared__ float sm[];
    float* Qs    = sm;                 // [64][36]  Q[i][d]
    float* Ks    = Qs + 64*36;         // [32][68]  K^T[d][j]
    float* Vs    = Ks + 32*68;         // [256][68] V[c][j] (tf32 vals)
    float* Ss    = Vs + 256*68;        // [64][68]  P[i][j] (tf32 vals)
    float* pmax2 = Ss + 64*68;         // [2][64]
    float* psum2 = pmax2 + 128;        // [2][64]
    float* row_m = psum2 + 128;
    float* row_l = row_m + 64;
    float* row_sc= row_l + 64;
    float* row_rl= row_sc + 64;

    const int t  = threadIdx.x;
    const int w  = t >> 5, l = t & 31;
    const int g  = l >> 2, tig = l & 3;
    const int b  = blockIdx.y;
    const int i0 = blockIdx.x * TQ;
    const float* qg = g_proj + (size_t)b*PROWS*NPIX;
    const float* kg = qg + (size_t)32*NPIX;
    const float* vg = qg + (size_t)64*NPIX;

    #pragma unroll
    for (int it=0; it<8; it++){
        int e = it*256 + t;
        int d = e >> 6, i = e & 63;
        Qs[i*36 + d] = qg[(size_t)d*NPIX + i0 + i];
    }
    if (t < 64){ row_m[t] = -1e30f; row_l[t] = 0.f; }

    const int wb = w & 3, wc = w >> 2;     // QK: row-band 16, col-half 32
    const int m0 = wb*16, nqk0 = wc*32;
    const int c0 = w*32;                   // PV: 32-channel slab

    float d_acc[2][8][4];
    #pragma unroll
    for (int mt=0;mt<2;mt++)
        #pragma unroll
        for (int nt=0;nt<8;nt++)
            #pragma unroll
            for (int q=0;q<4;q++) d_acc[mt][nt][q] = 0.f;

    for (int j0=0; j0<NPIX; j0+=TK){
        __syncthreads();
        #pragma unroll
        for (int it=0; it<8; it++){
            int e = it*256 + t;
            int d = e >> 6, j = e & 63;
            Ks[d*68 + j] = kg[(size_t)d*NPIX + j0 + j];
        }
        #pragma unroll
        for (int it=0; it<16; it++){
            int e4 = it*256 + t;
            int c = e4 >> 4, j4 = (e4 & 15) << 2;
            *(float4*)&Vs[c*68 + j4] = *(const float4*)(vg + (size_t)c*NPIX + j0 + j4);
        }
        __syncthreads();

        // QK split-tf32: S slab 16x32 per warp
        float sfr[4][4];
        #pragma unroll
        for (int nt=0;nt<4;nt++)
            #pragma unroll
            for (int q=0;q<4;q++) sfr[nt][q] = 0.f;
        #pragma unroll
        for (int ks=0; ks<4; ks++){
            int k0 = ks*8;
            float a0 = Qs[(m0+g  )*36 + k0+tig];
            float a1 = Qs[(m0+g+8)*36 + k0+tig];
            float a2 = Qs[(m0+g  )*36 + k0+tig+4];
            float a3 = Qs[(m0+g+8)*36 + k0+tig+4];
            uint32_t ah[4] = { f2tf(a0), f2tf(a1), f2tf(a2), f2tf(a3) };
            uint32_t al[4] = { f2tf(a0-__uint_as_float(ah[0])), f2tf(a1-__uint_as_float(ah[1])),
                               f2tf(a2-__uint_as_float(ah[2])), f2tf(a3-__uint_as_float(ah[3])) };
            #pragma unroll
            for (int nt=0;nt<4;nt++){
                int jb = nqk0 + nt*8;
                float bv0 = Ks[(k0+tig  )*68 + jb+g];
                float bv1 = Ks[(k0+tig+4)*68 + jb+g];
                uint32_t bh0 = f2tf(bv0), bh1 = f2tf(bv1);
                uint32_t bl0 = f2tf(bv0-__uint_as_float(bh0));
                uint32_t bl1 = f2tf(bv1-__uint_as_float(bh1));
                mma_tf32(sfr[nt], ah, bh0, bh1);
                mma_tf32(sfr[nt], al, bh0, bh1);
                mma_tf32(sfr[nt], ah, bl0, bl1);
            }
        }

        // softmax phase 1: partial row max
        float pm0 = sfr[0][0], pm1 = sfr[0][2];
        #pragma unroll
        for (int nt=0;nt<4;nt++){
            pm0 = fmaxf(pm0, fmaxf(sfr[nt][0], sfr[nt][1]));
            pm1 = fmaxf(pm1, fmaxf(sfr[nt][2], sfr[nt][3]));
        }
        pm0 = fmaxf(pm0, __shfl_xor_sync(0xffffffffu, pm0, 1));
        pm0 = fmaxf(pm0, __shfl_xor_sync(0xffffffffu, pm0, 2));
        pm1 = fmaxf(pm1, __shfl_xor_sync(0xffffffffu, pm1, 1));
        pm1 = fmaxf(pm1, __shfl_xor_sync(0xffffffffu, pm1, 2));
        if (tig == 0){
            pmax2[wc*64 + m0+g  ] = pm0;
            pmax2[wc*64 + m0+g+8] = pm1;
        }
        __syncthreads();

        // phase 2: P = exp(S - m_new), partial sums, store tf32 P
        {
            const int r0 = m0+g, r1 = m0+g+8;
            float mn0 = fmaxf(row_m[r0], fmaxf(pmax2[r0], pmax2[64+r0]));
            float mn1 = fmaxf(row_m[r1], fmaxf(pmax2[r1], pmax2[64+r1]));
            float ts0 = 0.f, ts1 = 0.f;
            #pragma unroll
            for (int nt=0;nt<4;nt++){
                int cb2 = nqk0 + nt*8 + 2*tig;
                float p00 = __expf(sfr[nt][0]-mn0), p01 = __expf(sfr[nt][1]-mn0);
                float p10 = __expf(sfr[nt][2]-mn1), p11 = __expf(sfr[nt][3]-mn1);
                ts0 += p00+p01;  ts1 += p10+p11;
                Ss[r0*68+cb2  ] = __uint_as_float(f2tf(p00));
                Ss[r0*68+cb2+1] = __uint_as_float(f2tf(p01));
                Ss[r1*68+cb2  ] = __uint_as_float(f2tf(p10));
                Ss[r1*68+cb2+1] = __uint_as_float(f2tf(p11));
            }
            ts0 += __shfl_xor_sync(0xffffffffu, ts0, 1);
            ts0 += __shfl_xor_sync(0xffffffffu, ts0, 2);
            ts1 += __shfl_xor_sync(0xffffffffu, ts1, 1);
            ts1 += __shfl_xor_sync(0xffffffffu, ts1, 2);
            if (tig == 0){ psum2[wc*64+r0] = ts0; psum2[wc*64+r1] = ts1; }
        }
        __syncthreads();

        // phase 3: row state (single writer per row)
        if (wc == 0 && tig == 0){
            #pragma unroll
            for (int h=0;h<2;h++){
                int r = m0 + g + h*8;
                float mo = row_m[r];
                float mn = fmaxf(mo, fmaxf(pmax2[r], pmax2[64+r]));
                float sc = __expf(mo - mn);
                row_sc[r] = sc;
                row_l[r]  = row_l[r]*sc + psum2[r] + psum2[64+r];
                row_m[r]  = mn;
            }
        }
        __syncthreads();

        // PV: rescale accumulators, then tf32 MMA
        float s0v[8], s1v[8];
        bool need = false;
        #pragma unroll
        for (int nt=0;nt<8;nt++){
            s0v[nt] = row_sc[nt*8 + 2*tig];
            s1v[nt] = row_sc[nt*8 + 2*tig + 1];
            need |= (s0v[nt] != 1.f) | (s1v[nt] != 1.f);
        }
        if (__ballot_sync(0xffffffffu, need)){
            #pragma unroll
            for (int mt=0;mt<2;mt++)
                #pragma unroll
                for (int nt=0;nt<8;nt++){
                    d_acc[mt][nt][0] *= s0v[nt];  d_acc[mt][nt][1] *= s1v[nt];
                    d_acc[mt][nt][2] *= s0v[nt];  d_acc[mt][nt][3] *= s1v[nt];
                }
        }
        #pragma unroll
        for (int ks=0; ks<8; ks++){
            int k0 = ks*8;
            uint32_t A0[4], A1[4];
            A0[0] = __float_as_uint(Vs[(c0+g   )*68 + k0+tig  ]);
            A0[1] = __float_as_uint(Vs[(c0+g+8 )*68 + k0+tig  ]);
            A0[2] = __float_as_uint(Vs[(c0+g   )*68 + k0+tig+4]);
            A0[3] = __float_as_uint(Vs[(c0+g+8 )*68 + k0+tig+4]);
            A1[0] = __float_as_uint(Vs[(c0+g+16)*68 + k0+tig  ]);
            A1[1] = __float_as_uint(Vs[(c0+g+24)*68 + k0+tig  ]);
            A1[2] = __float_as_uint(Vs[(c0+g+16)*68 + k0+tig+4]);
            A1[3] = __float_as_uint(Vs[(c0+g+24)*68 + k0+tig+4]);
            #pragma unroll
            for (int nt=0;nt<8;nt++){
                uint32_t b0 = __float_as_uint(Ss[(nt*8+g)*68 + k0+tig  ]);
                uint32_t b1 = __float_as_uint(Ss[(nt*8+g)*68 + k0+tig+4]);
                mma_tf32(d_acc[0][nt], A0, b0, b1);
                mma_tf32(d_acc[1][nt], A1, b0, b1);
            }
        }
    }

    // epilogue
    __syncthreads();
    if (t < 64) row_rl[t] = 1.f / row_l[t];
    __syncthreads();

    const float gam = gamma[0];
    float rl0[8], rl1[8];
    #pragma unroll
    for (int nt=0;nt<8;nt++){
        rl0[nt] = row_rl[nt*8 + 2*tig];
        rl1[nt] = row_rl[nt*8 + 2*tig + 1];
    }
    const int cta = b*NQT + blockIdx.x;
    #pragma unroll
    for (int mt=0;mt<2;mt++){
        #pragma unroll
        for (int h=0;h<2;h++){
            int c = c0 + mt*16 + g + h*8;
            size_t base = ((size_t)b*CCH + c)*NPIX + i0;
            float accs = 0.f, accq = 0.f;
            #pragma unroll
            for (int nt=0;nt<8;nt++){
                int i = nt*8 + 2*tig;
                float2 xv = *(const float2*)(x + base + i);
                float y0 = gam*d_acc[mt][nt][h*2+0]*rl0[nt] + xv.x;
                float y1 = gam*d_acc[mt][nt][h*2+1]*rl1[nt] + xv.y;
                *(float2*)(g_y + base + i) = make_float2(y0, y1);
                accs += y0 + y1;
                accq += y0*y0 + y1*y1;
            }
            accs += __shfl_xor_sync(0xffffffffu, accs, 1);
            accs += __shfl_xor_sync(0xffffffffu, accs, 2);
            accq += __shfl_xor_sync(0xffffffffu, accq, 1);
            accq += __shfl_xor_sync(0xffffffffu, accq, 2);
            if (tig == 0){
                g_psum[cta*CCH + c] = accs;
                g_psq [cta*CCH + c] = accq;
            }
        }
    }
}

// ---------------- Kernel C1: BN stat reduce ---------------------------------
__global__ __launch_bounds__(256) void bnstat_kernel(
    const float* __restrict__ bnw, const float* __restrict__ bnb)
{
    __shared__ float ss[256], sq[256];
    const int c = blockIdx.x, t = threadIdx.x;
    float s = g_psum[t*CCH + c] + g_psum[(t+256)*CCH + c];
    float q = g_psq [t*CCH + c] + g_psq [(t+256)*CCH + c];
    ss[t]=s; sq[t]=q;
    __syncthreads();
    for (int off=128; off>0; off>>=1){
        if (t<off){ ss[t]+=ss[t+off]; sq[t]+=sq[t+off]; }
        __syncthreads();
    }
    if (t==0){
        const float inv = 1.f/32768.f;
        float mean = ss[0]*inv;
        float var  = sq[0]*inv - mean*mean;
        float scale = bnw[c]*rsqrtf(var + 1e-5f);
        g_bn[c]       = scale;
        g_bn[CCH + c] = bnb[c] - mean*scale;
    }
}

// ---------------- Kernel C2: BN apply + ReLU --------------------------------
__global__ __launch_bounds__(256) void bnapply_kernel(float* __restrict__ out)
{
    int idx = blockIdx.x*256 + threadIdx.x;
    int c = (idx >> 10) & 255;
    float scale = g_bn[c], shift = g_bn[CCH + c];
    float4 y = ((const float4*)g_y)[idx];
    float4 o;
    o.x = fmaxf(y.x*scale + shift, 0.f);
    o.y = fmaxf(y.y*scale + shift, 0.f);
    o.z = fmaxf(y.z*scale + shift, 0.f);
    o.w = fmaxf(y.w*scale + shift, 0.f);
    ((float4*)out)[idx] = o;
}

// ---------------------------------------------------------------------------
extern "C" void kernel_launch(void* const* d_in, const int* in_sizes, int n_in,
                              void* d_out, int out_size)
{
    const float* x     = (const float*)d_in[0];
    const float* wq    = (const float*)d_in[1];
    const float* bq    = (const float*)d_in[2];
    const float* wk    = (const float*)d_in[3];
    const float* bk    = (const float*)d_in[4];
    const float* wv    = (const float*)d_in[5];
    const float* bv    = (const float*)d_in[6];
    const float* gamma = (const float*)d_in[7];
    const float* bnw   = (const float*)d_in[8];
    const float* bnb   = (const float*)d_in[9];
    float* out = (float*)d_out;

    dim3 gA(NPIX/128, PROWS/64, BATCH);
    proj_kernel<<<gA, 256>>>(x, wq, bq, wk, bk, wv, bv);

    const int attn_smem = (64*36 + 32*68 + 256*68 + 64*68 + 128+128 + 64*4) * 4; // 106,752 B
    cudaFuncSetAttribute(attn_kernel, cudaFuncAttributeMaxDynamicSharedMemorySize, attn_smem);
    attn_kernel<<<dim3(NQT, BATCH), 256, attn_smem>>>(x, gamma);

    bnstat_kernel<<<CCH, 256>>>(bnw, bnb);

    bnapply_kernel<<<(BATCH*CCH*NPIX)/(256*4), 256>>>(out);
}

// round 8
// speedup vs baseline: 4.1185x; 1.3513x over previous
#include <cuda_runtime.h>
#include <cuda_bf16.h>
#include <cstdint>

#define BATCH 8
#define CCH   256
#define NPIX  4096
#define TQ    64
#define TK    64
#define NQT   (NPIX/TQ)
#define NCTA_ATTN (BATCH*NQT)

__device__ __align__(16) float g_proj[(size_t)BATCH*64*NPIX];          // rows 0-31 q, 32-63 k (fp32)
__device__ __align__(16) __nv_bfloat16 g_vb[(size_t)BATCH*CCH*NPIX];   // V in bf16
__device__ __align__(16) float g_y[(size_t)BATCH*CCH*NPIX];
__device__ __align__(16) float g_psum[NCTA_ATTN*CCH];
__device__ __align__(16) float g_psq[NCTA_ATTN*CCH];
__device__ __align__(16) float g_bn[2*CCH];

__device__ __forceinline__ uint32_t f2tf(float f){
    uint32_t r; asm("cvt.rna.tf32.f32 %0, %1;" : "=r"(r) : "f"(f)); return r;
}
__device__ __forceinline__ uint32_t bf2pack(float lo, float hi){
    uint32_t r; asm("cvt.rn.bf16x2.f32 %0, %1, %2;" : "=r"(r) : "f"(hi), "f"(lo)); return r;
}
__device__ __forceinline__ void mma_tf32(float* d, const uint32_t* a, uint32_t b0, uint32_t b1){
    asm("mma.sync.aligned.m16n8k8.row.col.f32.tf32.tf32.f32 "
        "{%0,%1,%2,%3},{%4,%5,%6,%7},{%8,%9},{%0,%1,%2,%3};"
        : "+f"(d[0]), "+f"(d[1]), "+f"(d[2]), "+f"(d[3])
        : "r"(a[0]), "r"(a[1]), "r"(a[2]), "r"(a[3]), "r"(b0), "r"(b1));
}
__device__ __forceinline__ void mma_bf16(float* d, const uint32_t* a, uint32_t b0, uint32_t b1){
    asm("mma.sync.aligned.m16n8k16.row.col.f32.bf16.bf16.f32 "
        "{%0,%1,%2,%3},{%4,%5,%6,%7},{%8,%9},{%0,%1,%2,%3};"
        : "+f"(d[0]), "+f"(d[1]), "+f"(d[2]), "+f"(d[3])
        : "r"(a[0]), "r"(a[1]), "r"(a[2]), "r"(a[3]), "r"(b0), "r"(b1));
}

// ---------------- Kernel A: projection GEMM -------------------------------
// Q/K rows -> g_proj fp32.  V rows -> g_vb bf16.
__global__ __launch_bounds__(256) void proj_kernel(
    const float* __restrict__ x,
    const float* __restrict__ wq, const float* __restrict__ bq,
    const float* __restrict__ wk, const float* __restrict__ bk,
    const float* __restrict__ wv, const float* __restrict__ bv)
{
    __shared__ float Wt[32*64];
    __shared__ float Xt[32*128];
    const int t  = threadIdx.x;
    const int n0 = blockIdx.x*128;
    const int rowbase = blockIdx.y*64;
    const int b  = blockIdx.z;
    const int cg = t & 31, rg = t >> 5;
    const int col = cg*4;
    const float* xb = x + (size_t)b*CCH*NPIX;

    float4 acc[8];
    #pragma unroll
    for (int i=0;i<8;i++) acc[i] = make_float4(0.f,0.f,0.f,0.f);

    for (int k0=0;k0<CCH;k0+=32){
        __syncthreads();
        #pragma unroll
        for (int i=0;i<2;i++){
            int idx = t*2+i;
            int r = idx >> 3, kc = idx & 7;
            int grow = rowbase + r;
            const float* wsrc; int lrow;
            if (grow < 32)      { wsrc = wq; lrow = grow; }
            else if (grow < 64) { wsrc = wk; lrow = grow-32; }
            else                { wsrc = wv; lrow = grow-64; }
            float4 wv4 = *(const float4*)(wsrc + (size_t)lrow*CCH + k0 + kc*4);
            Wt[(kc*4+0)*64 + r] = wv4.x;
            Wt[(kc*4+1)*64 + r] = wv4.y;
            Wt[(kc*4+2)*64 + r] = wv4.z;
            Wt[(kc*4+3)*64 + r] = wv4.w;
        }
        #pragma unroll
        for (int i=0;i<4;i++){
            int idx = i*256 + t;
            int kk = idx >> 5, cc = (idx & 31)*4;
            *(float4*)&Xt[kk*128 + cc] = *(const float4*)(xb + (size_t)(k0+kk)*NPIX + n0 + cc);
        }
        __syncthreads();
        #pragma unroll
        for (int kk=0;kk<32;kk++){
            float4 xv = *(float4*)&Xt[kk*128 + col];
            float4 wa = *(float4*)&Wt[kk*64 + rg*8];
            float4 wb = *(float4*)&Wt[kk*64 + rg*8 + 4];
            float wr[8] = {wa.x,wa.y,wa.z,wa.w,wb.x,wb.y,wb.z,wb.w};
            #pragma unroll
            for (int i=0;i<8;i++){
                acc[i].x += wr[i]*xv.x;  acc[i].y += wr[i]*xv.y;
                acc[i].z += wr[i]*xv.z;  acc[i].w += wr[i]*xv.w;
            }
        }
    }
    #pragma unroll
    for (int i=0;i<8;i++){
        int grow = rowbase + rg*8 + i;
        float bias;
        if (grow < 32)      bias = bq[grow];
        else if (grow < 64) bias = bk[grow-32];
        else                bias = bv[grow-64];
        float4 o = acc[i];
        o.x += bias; o.y += bias; o.z += bias; o.w += bias;
        if (grow < 64){
            *(float4*)(g_proj + ((size_t)b*64 + grow)*NPIX + n0 + col) = o;
        } else {
            uint2 pk;
            pk.x = bf2pack(o.x, o.y);
            pk.y = bf2pack(o.z, o.w);
            *(uint2*)&g_vb[((size_t)b*CCH + (grow-64))*NPIX + n0 + col] = pk;
        }
    }
}

// ---------------- Kernel B: flash attention -------------------------------
// QK: split-tf32 (3 chains).  PV: bf16 m16n8k16, O^T[c][i] = V[c][j]*P[i][j].
// 256 thr (8 warps), grid (64,8), ~66KB smem, 2 CTAs/SM.
#define VSTR 72
__global__ __launch_bounds__(256,2) void attn_kernel(
    const float* __restrict__ x, const float* __restrict__ gamma)
{
    extern __shared__ char smraw[];
    float* Qs  = (float*)smraw;                     // [64][36] fp32
    float* Ks  = Qs + 64*36;                        // [32][68] fp32
    __nv_bfloat16* Vb = (__nv_bfloat16*)(Ks + 32*68);     // [256][72] bf16
    __nv_bfloat16* Pb = Vb + 256*VSTR;              // [64][72] bf16
    float* pmax2 = (float*)(Pb + 64*VSTR);          // [2][64]
    float* psum2 = pmax2 + 128;                     // [2][64]
    float* row_m = psum2 + 128;
    float* row_l = row_m + 64;
    float* row_sc= row_l + 64;
    float* row_rl= row_sc + 64;

    const int t  = threadIdx.x;
    const int w  = t >> 5, l = t & 31;
    const int g  = l >> 2, tig = l & 3;
    const int b  = blockIdx.y;
    const int i0 = blockIdx.x * TQ;
    const float* qg = g_proj + (size_t)b*64*NPIX;
    const float* kg = qg + (size_t)32*NPIX;
    const __nv_bfloat16* vbg = g_vb + (size_t)b*CCH*NPIX;

    #pragma unroll
    for (int it=0; it<8; it++){
        int e = it*256 + t;
        int d = e >> 6, i = e & 63;
        Qs[i*36 + d] = qg[(size_t)d*NPIX + i0 + i];
    }
    if (t < 64){ row_m[t] = -1e30f; row_l[t] = 0.f; }

    const int wb = w & 3, wc = w >> 2;
    const int m0 = wb*16, nqk0 = wc*32;
    const int c0 = w*32;

    float d_acc[2][8][4];
    #pragma unroll
    for (int mt=0;mt<2;mt++)
        #pragma unroll
        for (int nt=0;nt<8;nt++)
            #pragma unroll
            for (int q=0;q<4;q++) d_acc[mt][nt][q] = 0.f;

    for (int j0=0; j0<NPIX; j0+=TK){
        __syncthreads();
        #pragma unroll
        for (int it=0; it<8; it++){
            int e = it*256 + t;
            int d = e >> 6, j = e & 63;
            Ks[d*68 + j] = kg[(size_t)d*NPIX + j0 + j];
        }
        // V tile bf16: [256][VSTR], 16B chunks
        #pragma unroll
        for (int it=0; it<8; it++){
            int e = it*256 + t;
            int c = e >> 3, q = e & 7;
            *(uint4*)&Vb[c*VSTR + q*8] = *(const uint4*)(vbg + (size_t)c*NPIX + j0 + q*8);
        }
        __syncthreads();

        // ---- QK split-tf32: S slab 16x32 per warp ----
        float sfr[4][4];
        #pragma unroll
        for (int nt=0;nt<4;nt++)
            #pragma unroll
            for (int q=0;q<4;q++) sfr[nt][q] = 0.f;
        #pragma unroll
        for (int ks=0; ks<4; ks++){
            int k0 = ks*8;
            float a0 = Qs[(m0+g  )*36 + k0+tig];
            float a1 = Qs[(m0+g+8)*36 + k0+tig];
            float a2 = Qs[(m0+g  )*36 + k0+tig+4];
            float a3 = Qs[(m0+g+8)*36 + k0+tig+4];
            uint32_t ah[4] = { f2tf(a0), f2tf(a1), f2tf(a2), f2tf(a3) };
            uint32_t al[4] = { f2tf(a0-__uint_as_float(ah[0])), f2tf(a1-__uint_as_float(ah[1])),
                               f2tf(a2-__uint_as_float(ah[2])), f2tf(a3-__uint_as_float(ah[3])) };
            #pragma unroll
            for (int nt=0;nt<4;nt++){
                int jb = nqk0 + nt*8;
                float bv0 = Ks[(k0+tig  )*68 + jb+g];
                float bv1 = Ks[(k0+tig+4)*68 + jb+g];
                uint32_t bh0 = f2tf(bv0), bh1 = f2tf(bv1);
                uint32_t bl0 = f2tf(bv0-__uint_as_float(bh0));
                uint32_t bl1 = f2tf(bv1-__uint_as_float(bh1));
                mma_tf32(sfr[nt], ah, bh0, bh1);
                mma_tf32(sfr[nt], al, bh0, bh1);
                mma_tf32(sfr[nt], ah, bl0, bl1);
            }
        }

        // softmax phase 1: partial row max
        float pm0 = sfr[0][0], pm1 = sfr[0][2];
        #pragma unroll
        for (int nt=0;nt<4;nt++){
            pm0 = fmaxf(pm0, fmaxf(sfr[nt][0], sfr[nt][1]));
            pm1 = fmaxf(pm1, fmaxf(sfr[nt][2], sfr[nt][3]));
        }
        pm0 = fmaxf(pm0, __shfl_xor_sync(0xffffffffu, pm0, 1));
        pm0 = fmaxf(pm0, __shfl_xor_sync(0xffffffffu, pm0, 2));
        pm1 = fmaxf(pm1, __shfl_xor_sync(0xffffffffu, pm1, 1));
        pm1 = fmaxf(pm1, __shfl_xor_sync(0xffffffffu, pm1, 2));
        if (tig == 0){
            pmax2[wc*64 + m0+g  ] = pm0;
            pmax2[wc*64 + m0+g+8] = pm1;
        }
        __syncthreads();

        // phase 2: P = exp(S - m_new), partial sums, store bf16 P
        {
            const int r0 = m0+g, r1 = m0+g+8;
            float mn0 = fmaxf(row_m[r0], fmaxf(pmax2[r0], pmax2[64+r0]));
            float mn1 = fmaxf(row_m[r1], fmaxf(pmax2[r1], pmax2[64+r1]));
            float ts0 = 0.f, ts1 = 0.f;
            #pragma unroll
            for (int nt=0;nt<4;nt++){
                int cb2 = nqk0 + nt*8 + 2*tig;
                float p00 = __expf(sfr[nt][0]-mn0), p01 = __expf(sfr[nt][1]-mn0);
                float p10 = __expf(sfr[nt][2]-mn1), p11 = __expf(sfr[nt][3]-mn1);
                ts0 += p00+p01;  ts1 += p10+p11;
                *(uint32_t*)&Pb[r0*VSTR + cb2] = bf2pack(p00, p01);
                *(uint32_t*)&Pb[r1*VSTR + cb2] = bf2pack(p10, p11);
            }
            ts0 += __shfl_xor_sync(0xffffffffu, ts0, 1);
            ts0 += __shfl_xor_sync(0xffffffffu, ts0, 2);
            ts1 += __shfl_xor_sync(0xffffffffu, ts1, 1);
            ts1 += __shfl_xor_sync(0xffffffffu, ts1, 2);
            if (tig == 0){ psum2[wc*64+r0] = ts0; psum2[wc*64+r1] = ts1; }
        }
        __syncthreads();

        // phase 3: row state (single writer per row)
        if (wc == 0 && tig == 0){
            #pragma unroll
            for (int h=0;h<2;h++){
                int r = m0 + g + h*8;
                float mo = row_m[r];
                float mn = fmaxf(mo, fmaxf(pmax2[r], pmax2[64+r]));
                float sc = __expf(mo - mn);
                row_sc[r] = sc;
                row_l[r]  = row_l[r]*sc + psum2[r] + psum2[64+r];
                row_m[r]  = mn;
            }
        }
        __syncthreads();

        // ---- PV: rescale accumulators, then bf16 m16n8k16 MMA ----
        float s0v[8], s1v[8];
        bool need = false;
        #pragma unroll
        for (int nt=0;nt<8;nt++){
            s0v[nt] = row_sc[nt*8 + 2*tig];
            s1v[nt] = row_sc[nt*8 + 2*tig + 1];
            need |= (s0v[nt] != 1.f) | (s1v[nt] != 1.f);
        }
        if (__ballot_sync(0xffffffffu, need)){
            #pragma unroll
            for (int mt=0;mt<2;mt++)
                #pragma unroll
                for (int nt=0;nt<8;nt++){
                    d_acc[mt][nt][0] *= s0v[nt];  d_acc[mt][nt][1] *= s1v[nt];
                    d_acc[mt][nt][2] *= s0v[nt];  d_acc[mt][nt][3] *= s1v[nt];
                }
        }
        #pragma unroll
        for (int ks=0; ks<4; ks++){
            int k0 = ks*16;
            uint32_t A0[4], A1[4];
            A0[0] = *(const uint32_t*)&Vb[(c0+g   )*VSTR + k0+2*tig  ];
            A0[1] = *(const uint32_t*)&Vb[(c0+g+8 )*VSTR + k0+2*tig  ];
            A0[2] = *(const uint32_t*)&Vb[(c0+g   )*VSTR + k0+2*tig+8];
            A0[3] = *(const uint32_t*)&Vb[(c0+g+8 )*VSTR + k0+2*tig+8];
            A1[0] = *(const uint32_t*)&Vb[(c0+g+16)*VSTR + k0+2*tig  ];
            A1[1] = *(const uint32_t*)&Vb[(c0+g+24)*VSTR + k0+2*tig  ];
            A1[2] = *(const uint32_t*)&Vb[(c0+g+16)*VSTR + k0+2*tig+8];
            A1[3] = *(const uint32_t*)&Vb[(c0+g+24)*VSTR + k0+2*tig+8];
            #pragma unroll
            for (int nt=0;nt<8;nt++){
                uint32_t b0 = *(const uint32_t*)&Pb[(nt*8+g)*VSTR + k0+2*tig  ];
                uint32_t b1 = *(const uint32_t*)&Pb[(nt*8+g)*VSTR + k0+2*tig+8];
                mma_bf16(d_acc[0][nt], A0, b0, b1);
                mma_bf16(d_acc[1][nt], A1, b0, b1);
            }
        }
    }

    // ---- epilogue ----
    __syncthreads();
    if (t < 64) row_rl[t] = 1.f / row_l[t];
    __syncthreads();

    const float gam = gamma[0];
    float rl0[8], rl1[8];
    #pragma unroll
    for (int nt=0;nt<8;nt++){
        rl0[nt] = row_rl[nt*8 + 2*tig];
        rl1[nt] = row_rl[nt*8 + 2*tig + 1];
    }
    const int cta = b*NQT + blockIdx.x;
    #pragma unroll
    for (int mt=0;mt<2;mt++){
        #pragma unroll
        for (int h=0;h<2;h++){
            int c = c0 + mt*16 + g + h*8;
            size_t base = ((size_t)b*CCH + c)*NPIX + i0;
            float accs = 0.f, accq = 0.f;
            #pragma unroll
            for (int nt=0;nt<8;nt++){
                int i = nt*8 + 2*tig;
                float2 xv = *(const float2*)(x + base + i);
                float y0 = gam*d_acc[mt][nt][h*2+0]*rl0[nt] + xv.x;
                float y1 = gam*d_acc[mt][nt][h*2+1]*rl1[nt] + xv.y;
                *(float2*)(g_y + base + i) = make_float2(y0, y1);
                accs += y0 + y1;
                accq += y0*y0 + y1*y1;
            }
            accs += __shfl_xor_sync(0xffffffffu, accs, 1);
            accs += __shfl_xor_sync(0xffffffffu, accs, 2);
            accq += __shfl_xor_sync(0xffffffffu, accq, 1);
            accq += __shfl_xor_sync(0xffffffffu, accq, 2);
            if (tig == 0){
                g_psum[cta*CCH + c] = accs;
                g_psq [cta*CCH + c] = accq;
            }
        }
    }
}

// ---------------- Kernel C1: BN stat reduce -------------------------------
__global__ __launch_bounds__(256) void bnstat_kernel(
    const float* __restrict__ bnw, const float* __restrict__ bnb)
{
    __shared__ float ss[256], sq[256];
    const int c = blockIdx.x, t = threadIdx.x;
    float s = g_psum[t*CCH + c] + g_psum[(t+256)*CCH + c];
    float q = g_psq [t*CCH + c] + g_psq [(t+256)*CCH + c];
    ss[t]=s; sq[t]=q;
    __syncthreads();
    for (int off=128; off>0; off>>=1){
        if (t<off){ ss[t]+=ss[t+off]; sq[t]+=sq[t+off]; }
        __syncthreads();
    }
    if (t==0){
        const float inv = 1.f/32768.f;
        float mean = ss[0]*inv;
        float var  = sq[0]*inv - mean*mean;
        float scale = bnw[c]*rsqrtf(var + 1e-5f);
        g_bn[c]       = scale;
        g_bn[CCH + c] = bnb[c] - mean*scale;
    }
}

// ---------------- Kernel C2: BN apply + ReLU ------------------------------
__global__ __launch_bounds__(256) void bnapply_kernel(float* __restrict__ out)
{
    int idx = blockIdx.x*256 + threadIdx.x;
    int c = (idx >> 10) & 255;
    float scale = g_bn[c], shift = g_bn[CCH + c];
    float4 y = ((const float4*)g_y)[idx];
    float4 o;
    o.x = fmaxf(y.x*scale + shift, 0.f);
    o.y = fmaxf(y.y*scale + shift, 0.f);
    o.z = fmaxf(y.z*scale + shift, 0.f);
    o.w = fmaxf(y.w*scale + shift, 0.f);
    ((float4*)out)[idx] = o;
}

// ---------------------------------------------------------------------------
extern "C" void kernel_launch(void* const* d_in, const int* in_sizes, int n_in,
                              void* d_out, int out_size)
{
    const float* x     = (const float*)d_in[0];
    const float* wq    = (const float*)d_in[1];
    const float* bq    = (const float*)d_in[2];
    const float* wk    = (const float*)d_in[3];
    const float* bk    = (const float*)d_in[4];
    const float* wv    = (const float*)d_in[5];
    const float* bv    = (const float*)d_in[6];
    const float* gamma = (const float*)d_in[7];
    const float* bnw   = (const float*)d_in[8];
    const float* bnb   = (const float*)d_in[9];
    float* out = (float*)d_out;

    dim3 gA(NPIX/128, 320/64, BATCH);
    proj_kernel<<<gA, 256>>>(x, wq, bq, wk, bk, wv, bv);

    const int attn_smem = (64*36 + 32*68)*4 + (256*72 + 64*72)*2 + (128+128+64*4)*4; // 66,048 B
    cudaFuncSetAttribute(attn_kernel, cudaFuncAttributeMaxDynamicSharedMemorySize, attn_smem);
    attn_kernel<<<dim3(NQT, BATCH), 256, attn_smem>>>(x, gamma);

    bnstat_kernel<<<CCH, 256>>>(bnw, bnb);

    bnapply_kernel<<<(BATCH*CCH*NPIX)/(256*4), 256>>>(out);
}

// round 9
// speedup vs baseline: 4.1593x; 1.0099x over previous
#include <cuda_runtime.h>
#include <cuda_fp16.h>
#include <cstdint>

#define BATCH 8
#define CCH   256
#define NPIX  4096
#define TQ    64
#define TK    64
#define NQT   (NPIX/TQ)
#define NCTA_ATTN (BATCH*NQT)

__device__ __align__(16) float g_proj[(size_t)BATCH*64*NPIX];   // rows 0-31 q, 32-63 k (fp32)
__device__ __align__(16) __half g_vh[(size_t)BATCH*CCH*NPIX];   // V in fp16
__device__ __align__(16) float g_y[(size_t)BATCH*CCH*NPIX];
__device__ __align__(16) float g_psum[NCTA_ATTN*CCH];
__device__ __align__(16) float g_psq[NCTA_ATTN*CCH];
__device__ __align__(16) float g_bn[2*CCH];

__device__ __forceinline__ uint32_t f2tf(float f){
    uint32_t r; asm("cvt.rna.tf32.f32 %0, %1;" : "=r"(r) : "f"(f)); return r;
}
__device__ __forceinline__ uint32_t f16pack(float lo, float hi){
    uint32_t r; asm("cvt.rn.f16x2.f32 %0, %1, %2;" : "=r"(r) : "f"(hi), "f"(lo)); return r;
}
__device__ __forceinline__ void mma_tf32(float* d, const uint32_t* a, uint32_t b0, uint32_t b1){
    asm("mma.sync.aligned.m16n8k8.row.col.f32.tf32.tf32.f32 "
        "{%0,%1,%2,%3},{%4,%5,%6,%7},{%8,%9},{%0,%1,%2,%3};"
        : "+f"(d[0]), "+f"(d[1]), "+f"(d[2]), "+f"(d[3])
        : "r"(a[0]), "r"(a[1]), "r"(a[2]), "r"(a[3]), "r"(b0), "r"(b1));
}
__device__ __forceinline__ void mma_f16(float* d, const uint32_t* a, uint32_t b0, uint32_t b1){
    asm("mma.sync.aligned.m16n8k16.row.col.f32.f16.f16.f32 "
        "{%0,%1,%2,%3},{%4,%5,%6,%7},{%8,%9},{%0,%1,%2,%3};"
        : "+f"(d[0]), "+f"(d[1]), "+f"(d[2]), "+f"(d[3])
        : "r"(a[0]), "r"(a[1]), "r"(a[2]), "r"(a[3]), "r"(b0), "r"(b1));
}

// ---------------- Kernel A: projection GEMM on tensor cores ----------------
// Per CTA: 64 rows x 128 px, K=256.  8 warps: 2(m) x 4(n), each m32 x n32.
// Row-tile 0 (Q/K rows): split-tf32 (3 chains) -> fp32 out.
// Row-tiles 1-4 (V rows): single tf32 -> fp16 out.
__global__ __launch_bounds__(256) void projmma_kernel(
    const float* __restrict__ x,
    const float* __restrict__ wq, const float* __restrict__ bq,
    const float* __restrict__ wk, const float* __restrict__ bk,
    const float* __restrict__ wv, const float* __restrict__ bv)
{
    __shared__ float Ws[64*36];    // W[row][k] rows local, stride 36
    __shared__ float Xs[32*136];   // X[k][px], stride 136
    const int t  = threadIdx.x;
    const int w  = t >> 5, l = t & 31;
    const int g  = l >> 2, tig = l & 3;
    const int wm = w & 1, wn = w >> 1;
    const int m0 = wm*32, nw0 = wn*32;
    const int n0 = blockIdx.x*128;
    const int rowbase = blockIdx.y*64;
    const int b  = blockIdx.z;
    const bool is_qk = (blockIdx.y == 0);
    const float* xb = x + (size_t)b*CCH*NPIX;

    float acc[2][4][4];
    #pragma unroll
    for (int mt=0;mt<2;mt++)
        #pragma unroll
        for (int nt=0;nt<4;nt++)
            #pragma unroll
            for (int q=0;q<4;q++) acc[mt][nt][q] = 0.f;

    for (int k0=0; k0<CCH; k0+=32){
        __syncthreads();
        // stage W tile [64][32]
        #pragma unroll
        for (int it=0; it<8; it++){
            int e = it*256 + t;
            int r = e >> 5, kk = e & 31;
            int grow = rowbase + r;
            const float* ws; int lr;
            if (grow < 32)      { ws = wq; lr = grow; }
            else if (grow < 64) { ws = wk; lr = grow-32; }
            else                { ws = wv; lr = grow-64; }
            Ws[r*36 + kk] = ws[(size_t)lr*CCH + k0 + kk];
        }
        // stage X tile [32][128]
        #pragma unroll
        for (int it=0; it<4; it++){
            int e = it*256 + t;
            int kk = e >> 5, c4 = (e & 31)*4;
            *(float4*)&Xs[kk*136 + c4] = *(const float4*)(xb + (size_t)(k0+kk)*NPIX + n0 + c4);
        }
        __syncthreads();
        #pragma unroll
        for (int ks=0; ks<4; ks++){
            int k8 = ks*8;
            uint32_t ah[2][4], al[2][4];
            #pragma unroll
            for (int mt=0;mt<2;mt++){
                int rb = m0 + mt*16;
                float a0 = Ws[(rb+g  )*36 + k8+tig];
                float a1 = Ws[(rb+g+8)*36 + k8+tig];
                float a2 = Ws[(rb+g  )*36 + k8+tig+4];
                float a3 = Ws[(rb+g+8)*36 + k8+tig+4];
                ah[mt][0]=f2tf(a0); ah[mt][1]=f2tf(a1); ah[mt][2]=f2tf(a2); ah[mt][3]=f2tf(a3);
                if (is_qk){
                    al[mt][0]=f2tf(a0-__uint_as_float(ah[mt][0]));
                    al[mt][1]=f2tf(a1-__uint_as_float(ah[mt][1]));
                    al[mt][2]=f2tf(a2-__uint_as_float(ah[mt][2]));
                    al[mt][3]=f2tf(a3-__uint_as_float(ah[mt][3]));
                }
            }
            uint32_t bh[4][2], bl[4][2];
            #pragma unroll
            for (int nt=0;nt<4;nt++){
                int jn = nw0 + nt*8 + g;
                float b0 = Xs[(k8+tig  )*136 + jn];
                float b1 = Xs[(k8+tig+4)*136 + jn];
                bh[nt][0]=f2tf(b0); bh[nt][1]=f2tf(b1);
                if (is_qk){
                    bl[nt][0]=f2tf(b0-__uint_as_float(bh[nt][0]));
                    bl[nt][1]=f2tf(b1-__uint_as_float(bh[nt][1]));
                }
            }
            #pragma unroll
            for (int mt=0;mt<2;mt++)
                #pragma unroll
                for (int nt=0;nt<4;nt++){
                    mma_tf32(acc[mt][nt], ah[mt], bh[nt][0], bh[nt][1]);
                    if (is_qk){
                        mma_tf32(acc[mt][nt], al[mt], bh[nt][0], bh[nt][1]);
                        mma_tf32(acc[mt][nt], ah[mt], bl[nt][0], bl[nt][1]);
                    }
                }
        }
    }
    // epilogue with bias
    #pragma unroll
    for (int mt=0;mt<2;mt++){
        #pragma unroll
        for (int h=0;h<2;h++){
            int lrow = m0 + mt*16 + g + h*8;
            int grow = rowbase + lrow;
            float bias;
            if (grow < 32)      bias = bq[grow];
            else if (grow < 64) bias = bk[grow-32];
            else                bias = bv[grow-64];
            #pragma unroll
            for (int nt=0;nt<4;nt++){
                int pix = n0 + nw0 + nt*8 + 2*tig;
                float v0 = acc[mt][nt][h*2+0] + bias;
                float v1 = acc[mt][nt][h*2+1] + bias;
                if (is_qk){
                    *(float2*)(g_proj + ((size_t)b*64 + grow)*NPIX + pix) = make_float2(v0, v1);
                } else {
                    uint32_t pk = f16pack(v0, v1);
                    *(uint32_t*)&g_vh[((size_t)b*CCH + (grow-64))*NPIX + pix] = pk;
                }
            }
        }
    }
}

// ---------------- Kernel B: flash attention -------------------------------
// QK: split-tf32 (3 chains).  PV: fp16 m16n8k16, O^T[c][i] = V[c][j]*P[i][j].
// 256 thr (8 warps), grid (64,8), ~66KB smem, 2 CTAs/SM.
#define VSTR 72
__global__ __launch_bounds__(256,2) void attn_kernel(
    const float* __restrict__ x, const float* __restrict__ gamma)
{
    extern __shared__ char smraw[];
    float* Qs  = (float*)smraw;                  // [64][36] fp32
    float* Ks  = Qs + 64*36;                     // [32][68] fp32
    __half* Vb = (__half*)(Ks + 32*68);          // [256][72] fp16
    __half* Pb = Vb + 256*VSTR;                  // [64][72] fp16
    float* pmax2 = (float*)(Pb + 64*VSTR);       // [2][64]
    float* psum2 = pmax2 + 128;                  // [2][64]
    float* row_m = psum2 + 128;
    float* row_l = row_m + 64;
    float* row_sc= row_l + 64;
    float* row_rl= row_sc + 64;

    const int t  = threadIdx.x;
    const int w  = t >> 5, l = t & 31;
    const int g  = l >> 2, tig = l & 3;
    const int b  = blockIdx.y;
    const int i0 = blockIdx.x * TQ;
    const float* qg = g_proj + (size_t)b*64*NPIX;
    const float* kg = qg + (size_t)32*NPIX;
    const __half* vhg = g_vh + (size_t)b*CCH*NPIX;

    #pragma unroll
    for (int it=0; it<8; it++){
        int e = it*256 + t;
        int d = e >> 6, i = e & 63;
        Qs[i*36 + d] = qg[(size_t)d*NPIX + i0 + i];
    }
    if (t < 64){ row_m[t] = -1e30f; row_l[t] = 0.f; }

    const int wb = w & 3, wc = w >> 2;
    const int m0 = wb*16, nqk0 = wc*32;
    const int c0 = w*32;

    float d_acc[2][8][4];
    #pragma unroll
    for (int mt=0;mt<2;mt++)
        #pragma unroll
        for (int nt=0;nt<8;nt++)
            #pragma unroll
            for (int q=0;q<4;q++) d_acc[mt][nt][q] = 0.f;

    for (int j0=0; j0<NPIX; j0+=TK){
        __syncthreads();
        #pragma unroll
        for (int it=0; it<8; it++){
            int e = it*256 + t;
            int d = e >> 6, j = e & 63;
            Ks[d*68 + j] = kg[(size_t)d*NPIX + j0 + j];
        }
        #pragma unroll
        for (int it=0; it<8; it++){
            int e = it*256 + t;
            int c = e >> 3, q = e & 7;
            *(uint4*)&Vb[c*VSTR + q*8] = *(const uint4*)(vhg + (size_t)c*NPIX + j0 + q*8);
        }
        __syncthreads();

        // ---- QK split-tf32: S slab 16x32 per warp ----
        float sfr[4][4];
        #pragma unroll
        for (int nt=0;nt<4;nt++)
            #pragma unroll
            for (int q=0;q<4;q++) sfr[nt][q] = 0.f;
        #pragma unroll
        for (int ks=0; ks<4; ks++){
            int k0 = ks*8;
            float a0 = Qs[(m0+g  )*36 + k0+tig];
            float a1 = Qs[(m0+g+8)*36 + k0+tig];
            float a2 = Qs[(m0+g  )*36 + k0+tig+4];
            float a3 = Qs[(m0+g+8)*36 + k0+tig+4];
            uint32_t ah[4] = { f2tf(a0), f2tf(a1), f2tf(a2), f2tf(a3) };
            uint32_t al[4] = { f2tf(a0-__uint_as_float(ah[0])), f2tf(a1-__uint_as_float(ah[1])),
                               f2tf(a2-__uint_as_float(ah[2])), f2tf(a3-__uint_as_float(ah[3])) };
            #pragma unroll
            for (int nt=0;nt<4;nt++){
                int jb = nqk0 + nt*8;
                float bv0 = Ks[(k0+tig  )*68 + jb+g];
                float bv1 = Ks[(k0+tig+4)*68 + jb+g];
                uint32_t bh0 = f2tf(bv0), bh1 = f2tf(bv1);
                uint32_t bl0 = f2tf(bv0-__uint_as_float(bh0));
                uint32_t bl1 = f2tf(bv1-__uint_as_float(bh1));
                mma_tf32(sfr[nt], ah, bh0, bh1);
                mma_tf32(sfr[nt], al, bh0, bh1);
                mma_tf32(sfr[nt], ah, bl0, bl1);
            }
        }

        // softmax phase 1: partial row max
        float pm0 = sfr[0][0], pm1 = sfr[0][2];
        #pragma unroll
        for (int nt=0;nt<4;nt++){
            pm0 = fmaxf(pm0, fmaxf(sfr[nt][0], sfr[nt][1]));
            pm1 = fmaxf(pm1, fmaxf(sfr[nt][2], sfr[nt][3]));
        }
        pm0 = fmaxf(pm0, __shfl_xor_sync(0xffffffffu, pm0, 1));
        pm0 = fmaxf(pm0, __shfl_xor_sync(0xffffffffu, pm0, 2));
        pm1 = fmaxf(pm1, __shfl_xor_sync(0xffffffffu, pm1, 1));
        pm1 = fmaxf(pm1, __shfl_xor_sync(0xffffffffu, pm1, 2));
        if (tig == 0){
            pmax2[wc*64 + m0+g  ] = pm0;
            pmax2[wc*64 + m0+g+8] = pm1;
        }
        __syncthreads();

        // phase 2: P = exp(S - m_new), partial sums, store fp16 P
        {
            const int r0 = m0+g, r1 = m0+g+8;
            float mn0 = fmaxf(row_m[r0], fmaxf(pmax2[r0], pmax2[64+r0]));
            float mn1 = fmaxf(row_m[r1], fmaxf(pmax2[r1], pmax2[64+r1]));
            float ts0 = 0.f, ts1 = 0.f;
            #pragma unroll
            for (int nt=0;nt<4;nt++){
                int cb2 = nqk0 + nt*8 + 2*tig;
                float p00 = __expf(sfr[nt][0]-mn0), p01 = __expf(sfr[nt][1]-mn0);
                float p10 = __expf(sfr[nt][2]-mn1), p11 = __expf(sfr[nt][3]-mn1);
                ts0 += p00+p01;  ts1 += p10+p11;
                *(uint32_t*)&Pb[r0*VSTR + cb2] = f16pack(p00, p01);
                *(uint32_t*)&Pb[r1*VSTR + cb2] = f16pack(p10, p11);
            }
            ts0 += __shfl_xor_sync(0xffffffffu, ts0, 1);
            ts0 += __shfl_xor_sync(0xffffffffu, ts0, 2);
            ts1 += __shfl_xor_sync(0xffffffffu, ts1, 1);
            ts1 += __shfl_xor_sync(0xffffffffu, ts1, 2);
            if (tig == 0){ psum2[wc*64+r0] = ts0; psum2[wc*64+r1] = ts1; }
        }
        __syncthreads();

        // phase 3: row state (single writer per row)
        if (wc == 0 && tig == 0){
            #pragma unroll
            for (int h=0;h<2;h++){
                int r = m0 + g + h*8;
                float mo = row_m[r];
                float mn = fmaxf(mo, fmaxf(pmax2[r], pmax2[64+r]));
                float sc = __expf(mo - mn);
                row_sc[r] = sc;
                row_l[r]  = row_l[r]*sc + psum2[r] + psum2[64+r];
                row_m[r]  = mn;
            }
        }
        __syncthreads();

        // ---- PV: rescale accumulators, then fp16 m16n8k16 MMA ----
        float s0v[8], s1v[8];
        bool need = false;
        #pragma unroll
        for (int nt=0;nt<8;nt++){
            s0v[nt] = row_sc[nt*8 + 2*tig];
            s1v[nt] = row_sc[nt*8 + 2*tig + 1];
            need |= (s0v[nt] != 1.f) | (s1v[nt] != 1.f);
        }
        if (__ballot_sync(0xffffffffu, need)){
            #pragma unroll
            for (int mt=0;mt<2;mt++)
                #pragma unroll
                for (int nt=0;nt<8;nt++){
                    d_acc[mt][nt][0] *= s0v[nt];  d_acc[mt][nt][1] *= s1v[nt];
                    d_acc[mt][nt][2] *= s0v[nt];  d_acc[mt][nt][3] *= s1v[nt];
                }
        }
        #pragma unroll
        for (int ks=0; ks<4; ks++){
            int k0 = ks*16;
            uint32_t A0[4], A1[4];
            A0[0] = *(const uint32_t*)&Vb[(c0+g   )*VSTR + k0+2*tig  ];
            A0[1] = *(const uint32_t*)&Vb[(c0+g+8 )*VSTR + k0+2*tig  ];
            A0[2] = *(const uint32_t*)&Vb[(c0+g   )*VSTR + k0+2*tig+8];
            A0[3] = *(const uint32_t*)&Vb[(c0+g+8 )*VSTR + k0+2*tig+8];
            A1[0] = *(const uint32_t*)&Vb[(c0+g+16)*VSTR + k0+2*tig  ];
            A1[1] = *(const uint32_t*)&Vb[(c0+g+24)*VSTR + k0+2*tig  ];
            A1[2] = *(const uint32_t*)&Vb[(c0+g+16)*VSTR + k0+2*tig+8];
            A1[3] = *(const uint32_t*)&Vb[(c0+g+24)*VSTR + k0+2*tig+8];
            #pragma unroll
            for (int nt=0;nt<8;nt++){
                uint32_t b0 = *(const uint32_t*)&Pb[(nt*8+g)*VSTR + k0+2*tig  ];
                uint32_t b1 = *(const uint32_t*)&Pb[(nt*8+g)*VSTR + k0+2*tig+8];
                mma_f16(d_acc[0][nt], A0, b0, b1);
                mma_f16(d_acc[1][nt], A1, b0, b1);
            }
        }
    }

    // ---- epilogue ----
    __syncthreads();
    if (t < 64) row_rl[t] = 1.f / row_l[t];
    __syncthreads();

    const float gam = gamma[0];
    float rl0[8], rl1[8];
    #pragma unroll
    for (int nt=0;nt<8;nt++){
        rl0[nt] = row_rl[nt*8 + 2*tig];
        rl1[nt] = row_rl[nt*8 + 2*tig + 1];
    }
    const int cta = b*NQT + blockIdx.x;
    #pragma unroll
    for (int mt=0;mt<2;mt++){
        #pragma unroll
        for (int h=0;h<2;h++){
            int c = c0 + mt*16 + g + h*8;
            size_t base = ((size_t)b*CCH + c)*NPIX + i0;
            float accs = 0.f, accq = 0.f;
            #pragma unroll
            for (int nt=0;nt<8;nt++){
                int i = nt*8 + 2*tig;
                float2 xv = *(const float2*)(x + base + i);
                float y0 = gam*d_acc[mt][nt][h*2+0]*rl0[nt] + xv.x;
                float y1 = gam*d_acc[mt][nt][h*2+1]*rl1[nt] + xv.y;
                *(float2*)(g_y + base + i) = make_float2(y0, y1);
                accs += y0 + y1;
                accq += y0*y0 + y1*y1;
            }
            accs += __shfl_xor_sync(0xffffffffu, accs, 1);
            accs += __shfl_xor_sync(0xffffffffu, accs, 2);
            accq += __shfl_xor_sync(0xffffffffu, accq, 1);
            accq += __shfl_xor_sync(0xffffffffu, accq, 2);
            if (tig == 0){
                g_psum[cta*CCH + c] = accs;
                g_psq [cta*CCH + c] = accq;
            }
        }
    }
}

// ---------------- Kernel C1: BN stat reduce -------------------------------
__global__ __launch_bounds__(256) void bnstat_kernel(
    const float* __restrict__ bnw, const float* __restrict__ bnb)
{
    __shared__ float ss[256], sq[256];
    const int c = blockIdx.x, t = threadIdx.x;
    float s = g_psum[t*CCH + c] + g_psum[(t+256)*CCH + c];
    float q = g_psq [t*CCH + c] + g_psq [(t+256)*CCH + c];
    ss[t]=s; sq[t]=q;
    __syncthreads();
    for (int off=128; off>0; off>>=1){
        if (t<off){ ss[t]+=ss[t+off]; sq[t]+=sq[t+off]; }
        __syncthreads();
    }
    if (t==0){
        const float inv = 1.f/32768.f;
        float mean = ss[0]*inv;
        float var  = sq[0]*inv - mean*mean;
        float scale = bnw[c]*rsqrtf(var + 1e-5f);
        g_bn[c]       = scale;
        g_bn[CCH + c] = bnb[c] - mean*scale;
    }
}

// ---------------- Kernel C2: BN apply + ReLU ------------------------------
__global__ __launch_bounds__(256) void bnapply_kernel(float* __restrict__ out)
{
    int idx = blockIdx.x*256 + threadIdx.x;
    int c = (idx >> 10) & 255;
    float scale = g_bn[c], shift = g_bn[CCH + c];
    float4 y = ((const float4*)g_y)[idx];
    float4 o;
    o.x = fmaxf(y.x*scale + shift, 0.f);
    o.y = fmaxf(y.y*scale + shift, 0.f);
    o.z = fmaxf(y.z*scale + shift, 0.f);
    o.w = fmaxf(y.w*scale + shift, 0.f);
    ((float4*)out)[idx] = o;
}

// ---------------------------------------------------------------------------
extern "C" void kernel_launch(void* const* d_in, const int* in_sizes, int n_in,
                              void* d_out, int out_size)
{
    const float* x     = (const float*)d_in[0];
    const float* wq    = (const float*)d_in[1];
    const float* bq    = (const float*)d_in[2];
    const float* wk    = (const float*)d_in[3];
    const float* bk    = (const float*)d_in[4];
    const float* wv    = (const float*)d_in[5];
    const float* bv    = (const float*)d_in[6];
    const float* gamma = (const float*)d_in[7];
    const float* bnw   = (const float*)d_in[8];
    const float* bnb   = (const float*)d_in[9];
    float* out = (float*)d_out;

    dim3 gA(NPIX/128, 5, BATCH);   // y=0: Q/K rows, y=1..4: V rows
    projmma_kernel<<<gA, 256>>>(x, wq, bq, wk, bk, wv, bv);

    const int attn_smem = (64*36 + 32*68)*4 + (256*VSTR + 64*VSTR)*2 + (128+128+64*4)*4; // 66,048 B
    cudaFuncSetAttribute(attn_kernel, cudaFuncAttributeMaxDynamicSharedMemorySize, attn_smem);
    attn_kernel<<<dim3(NQT, BATCH), 256, attn_smem>>>(x, gamma);

    bnstat_kernel<<<CCH, 256>>>(bnw, bnb);

    bnapply_kernel<<<(BATCH*CCH*NPIX)/(256*4), 256>>>(out);
}

// round 14
// speedup vs baseline: 4.8724x; 1.1714x over previous
#include <cuda_runtime.h>
#include <cuda_fp16.h>
#include <cstdint>

#define BATCH 8
#define CCH   256
#define NPIX  4096
#define TQ    64
#define TK    64
#define NQT   (NPIX/TQ)
#define NCTA_ATTN (BATCH*NQT)

__device__ __align__(16) float g_proj[(size_t)BATCH*64*NPIX];   // rows 0-31 q, 32-63 k (fp32)
__device__ __align__(16) __half g_vh[(size_t)BATCH*CCH*NPIX];   // V in fp16
__device__ __align__(16) float g_y[(size_t)BATCH*CCH*NPIX];
__device__ __align__(16) float g_psum[NCTA_ATTN*CCH];
__device__ __align__(16) float g_psq[NCTA_ATTN*CCH];
__device__ __align__(16) float g_bn[2*CCH];

__device__ __forceinline__ uint32_t f2tf(float f){
    uint32_t r; asm("cvt.rna.tf32.f32 %0, %1;" : "=r"(r) : "f"(f)); return r;
}
__device__ __forceinline__ uint32_t f16pack(float lo, float hi){
    uint32_t r; asm("cvt.rn.f16x2.f32 %0, %1, %2;" : "=r"(r) : "f"(hi), "f"(lo)); return r;
}
__device__ __forceinline__ void mma_tf32(float* d, const uint32_t* a, uint32_t b0, uint32_t b1){
    asm("mma.sync.aligned.m16n8k8.row.col.f32.tf32.tf32.f32 "
        "{%0,%1,%2,%3},{%4,%5,%6,%7},{%8,%9},{%0,%1,%2,%3};"
        : "+f"(d[0]), "+f"(d[1]), "+f"(d[2]), "+f"(d[3])
        : "r"(a[0]), "r"(a[1]), "r"(a[2]), "r"(a[3]), "r"(b0), "r"(b1));
}
__device__ __forceinline__ void mma_f16(float* d, const uint32_t* a, uint32_t b0, uint32_t b1){
    asm("mma.sync.aligned.m16n8k16.row.col.f32.f16.f16.f32 "
        "{%0,%1,%2,%3},{%4,%5,%6,%7},{%8,%9},{%0,%1,%2,%3};"
        : "+f"(d[0]), "+f"(d[1]), "+f"(d[2]), "+f"(d[3])
        : "r"(a[0]), "r"(a[1]), "r"(a[2]), "r"(a[3]), "r"(b0), "r"(b1));
}

// ---------------- Kernel A: projection GEMM on tensor cores ----------------
__global__ __launch_bounds__(256) void projmma_kernel(
    const float* __restrict__ x,
    const float* __restrict__ wq, const float* __restrict__ bq,
    const float* __restrict__ wk, const float* __restrict__ bk,
    const float* __restrict__ wv, const float* __restrict__ bv)
{
    __shared__ float Ws[64*36];
    __shared__ float Xs[32*136];
    const int t  = threadIdx.x;
    const int w  = t >> 5, l = t & 31;
    const int g  = l >> 2, tig = l & 3;
    const int wm = w & 1, wn = w >> 1;
    const int m0 = wm*32, nw0 = wn*32;
    const int n0 = blockIdx.x*128;
    const int rowbase = blockIdx.y*64;
    const int b  = blockIdx.z;
    const bool is_qk = (blockIdx.y == 0);
    const float* xb = x + (size_t)b*CCH*NPIX;

    float acc[2][4][4];
    #pragma unroll
    for (int mt=0;mt<2;mt++)
        #pragma unroll
        for (int nt=0;nt<4;nt++)
            #pragma unroll
            for (int q=0;q<4;q++) acc[mt][nt][q] = 0.f;

    for (int k0=0; k0<CCH; k0+=32){
        __syncthreads();
        #pragma unroll
        for (int it=0; it<8; it++){
            int e = it*256 + t;
            int r = e >> 5, kk = e & 31;
            int grow = rowbase + r;
            const float* ws; int lr;
            if (grow < 32)      { ws = wq; lr = grow; }
            else if (grow < 64) { ws = wk; lr = grow-32; }
            else                { ws = wv; lr = grow-64; }
            Ws[r*36 + kk] = ws[(size_t)lr*CCH + k0 + kk];
        }
        #pragma unroll
        for (int it=0; it<4; it++){
            int e = it*256 + t;
            int kk = e >> 5, c4 = (e & 31)*4;
            *(float4*)&Xs[kk*136 + c4] = *(const float4*)(xb + (size_t)(k0+kk)*NPIX + n0 + c4);
        }
        __syncthreads();
        #pragma unroll
        for (int ks=0; ks<4; ks++){
            int k8 = ks*8;
            uint32_t ah[2][4], al[2][4];
            #pragma unroll
            for (int mt=0;mt<2;mt++){
                int rb = m0 + mt*16;
                float a0 = Ws[(rb+g  )*36 + k8+tig];
                float a1 = Ws[(rb+g+8)*36 + k8+tig];
                float a2 = Ws[(rb+g  )*36 + k8+tig+4];
                float a3 = Ws[(rb+g+8)*36 + k8+tig+4];
                ah[mt][0]=f2tf(a0); ah[mt][1]=f2tf(a1); ah[mt][2]=f2tf(a2); ah[mt][3]=f2tf(a3);
                if (is_qk){
                    al[mt][0]=f2tf(a0-__uint_as_float(ah[mt][0]));
                    al[mt][1]=f2tf(a1-__uint_as_float(ah[mt][1]));
                    al[mt][2]=f2tf(a2-__uint_as_float(ah[mt][2]));
                    al[mt][3]=f2tf(a3-__uint_as_float(ah[mt][3]));
                }
            }
            uint32_t bh[4][2], bl[4][2];
            #pragma unroll
            for (int nt=0;nt<4;nt++){
                int jn = nw0 + nt*8 + g;
                float b0 = Xs[(k8+tig  )*136 + jn];
                float b1 = Xs[(k8+tig+4)*136 + jn];
                bh[nt][0]=f2tf(b0); bh[nt][1]=f2tf(b1);
                if (is_qk){
                    bl[nt][0]=f2tf(b0-__uint_as_float(bh[nt][0]));
                    bl[nt][1]=f2tf(b1-__uint_as_float(bh[nt][1]));
                }
            }
            #pragma unroll
            for (int mt=0;mt<2;mt++)
                #pragma unroll
                for (int nt=0;nt<4;nt++){
                    mma_tf32(acc[mt][nt], ah[mt], bh[nt][0], bh[nt][1]);
                    if (is_qk){
                        mma_tf32(acc[mt][nt], al[mt], bh[nt][0], bh[nt][1]);
                        mma_tf32(acc[mt][nt], ah[mt], bl[nt][0], bl[nt][1]);
                    }
                }
        }
    }
    #pragma unroll
    for (int mt=0;mt<2;mt++){
        #pragma unroll
        for (int h=0;h<2;h++){
            int lrow = m0 + mt*16 + g + h*8;
            int grow = rowbase + lrow;
            float bias;
            if (grow < 32)      bias = bq[grow];
            else if (grow < 64) bias = bk[grow-32];
            else                bias = bv[grow-64];
            #pragma unroll
            for (int nt=0;nt<4;nt++){
                int pix = n0 + nw0 + nt*8 + 2*tig;
                float v0 = acc[mt][nt][h*2+0] + bias;
                float v1 = acc[mt][nt][h*2+1] + bias;
                if (is_qk){
                    *(float2*)(g_proj + ((size_t)b*64 + grow)*NPIX + pix) = make_float2(v0, v1);
                } else {
                    *(uint32_t*)&g_vh[((size_t)b*CCH + (grow-64))*NPIX + pix] = f16pack(v0, v1);
                }
            }
        }
    }
}

// ---------------- Kernel B: flash attention -------------------------------
// QK: fp16-split (hi/lo, 3 chains of m16n8k16) -> near-fp32 scores.
// PV: fp16 m16n8k16, O^T[c][i] = V[c][j]*P[i][j].
// 256 thr (8 warps), grid (64,8), ~67KB smem, 2 CTAs/SM.
#define VSTR 72
#define QKS  20   /* uint32 stride for hi/lo pair arrays */
__global__ __launch_bounds__(256,2) void attn_kernel(
    const float* __restrict__ x, const float* __restrict__ gamma)
{
    extern __shared__ char smraw[];
    __half* Vb = (__half*)smraw;                     // [256][72] fp16
    __half* Pb = Vb + 256*VSTR;                      // [64][72] fp16
    uint32_t* Qh32 = (uint32_t*)(Pb + 64*VSTR);      // [64][20] fp16x2 hi
    uint32_t* Ql32 = Qh32 + 64*QKS;                  // lo
    uint32_t* Kh32 = Ql32 + 64*QKS;
    uint32_t* Kl32 = Kh32 + 64*QKS;
    float* pmax2 = (float*)(Kl32 + 64*QKS);          // [2][64]
    float* psum2 = pmax2 + 128;                      // [2][64]
    float* row_m = psum2 + 128;
    float* row_l = row_m + 64;
    float* row_sc= row_l + 64;
    float* row_rl= row_sc + 64;

    const int t  = threadIdx.x;
    const int w  = t >> 5, l = t & 31;
    const int g  = l >> 2, tig = l & 3;
    const int b  = blockIdx.y;
    const int i0 = blockIdx.x * TQ;
    const float* qg = g_proj + (size_t)b*64*NPIX;
    const float* kg = qg + (size_t)32*NPIX;
    const __half* vhg = g_vh + (size_t)b*CCH*NPIX;

    // stage Q hi/lo once: [64 rows][16 d-pairs], stride 20
    #pragma unroll
    for (int it=0; it<4; it++){
        int p = it*256 + t;
        int i = p & 63, dp = p >> 6;
        float v0 = qg[(size_t)(2*dp  )*NPIX + i0 + i];
        float v1 = qg[(size_t)(2*dp+1)*NPIX + i0 + i];
        __half h0 = __float2half_rn(v0), h1 = __float2half_rn(v1);
        __half2 hh = __halves2half2(h0, h1);
        Qh32[i*QKS + dp] = *(uint32_t*)&hh;
        __half l0 = __float2half_rn(v0 - __half2float(h0));
        __half l1 = __float2half_rn(v1 - __half2float(h1));
        __half2 ll = __halves2half2(l0, l1);
        Ql32[i*QKS + dp] = *(uint32_t*)&ll;
    }
    if (t < 64){ row_m[t] = -1e30f; row_l[t] = 0.f; }

    const int wb = w & 3, wc = w >> 2;
    const int m0 = wb*16, nqk0 = wc*32;
    const int c0 = w*32;

    float d_acc[2][8][4];
    #pragma unroll
    for (int mt=0;mt<2;mt++)
        #pragma unroll
        for (int nt=0;nt<8;nt++)
            #pragma unroll
            for (int q=0;q<4;q++) d_acc[mt][nt][q] = 0.f;

    for (int j0=0; j0<NPIX; j0+=TK){
        __syncthreads();
        // stage K hi/lo: [64 j][16 d-pairs]
        #pragma unroll
        for (int it=0; it<4; it++){
            int p = it*256 + t;
            int j = p & 63, dp = p >> 6;
            float v0 = kg[(size_t)(2*dp  )*NPIX + j0 + j];
            float v1 = kg[(size_t)(2*dp+1)*NPIX + j0 + j];
            __half h0 = __float2half_rn(v0), h1 = __float2half_rn(v1);
            __half2 hh = __halves2half2(h0, h1);
            Kh32[j*QKS + dp] = *(uint32_t*)&hh;
            __half l0 = __float2half_rn(v0 - __half2float(h0));
            __half l1 = __float2half_rn(v1 - __half2float(h1));
            __half2 ll = __halves2half2(l0, l1);
            Kl32[j*QKS + dp] = *(uint32_t*)&ll;
        }
        // stage V fp16: [256 c][72]
        #pragma unroll
        for (int it=0; it<8; it++){
            int e = it*256 + t;
            int c = e >> 3, q = e & 7;
            *(uint4*)&Vb[c*VSTR + q*8] = *(const uint4*)(vhg + (size_t)c*NPIX + j0 + q*8);
        }
        __syncthreads();

        // ---- QK fp16-split: S slab 16x32 per warp, 2x k16 steps ----
        float sfr[4][4];
        #pragma unroll
        for (int nt=0;nt<4;nt++)
            #pragma unroll
            for (int q=0;q<4;q++) sfr[nt][q] = 0.f;
        #pragma unroll
        for (int ks=0; ks<2; ks++){
            int kb = ks*8;
            uint32_t ah[4], alr[4];
            ah[0]  = Qh32[(m0+g  )*QKS + kb+tig];
            ah[1]  = Qh32[(m0+g+8)*QKS + kb+tig];
            ah[2]  = Qh32[(m0+g  )*QKS + kb+tig+4];
            ah[3]  = Qh32[(m0+g+8)*QKS + kb+tig+4];
            alr[0] = Ql32[(m0+g  )*QKS + kb+tig];
            alr[1] = Ql32[(m0+g+8)*QKS + kb+tig];
            alr[2] = Ql32[(m0+g  )*QKS + kb+tig+4];
            alr[3] = Ql32[(m0+g+8)*QKS + kb+tig+4];
            #pragma unroll
            for (int nt=0;nt<4;nt++){
                int jr = nqk0 + nt*8 + g;
                uint32_t bh0 = Kh32[jr*QKS + kb+tig], bh1 = Kh32[jr*QKS + kb+tig+4];
                uint32_t bl0 = Kl32[jr*QKS + kb+tig], bl1 = Kl32[jr*QKS + kb+tig+4];
                mma_f16(sfr[nt], ah,  bh0, bh1);
                mma_f16(sfr[nt], alr, bh0, bh1);
                mma_f16(sfr[nt], ah,  bl0, bl1);
            }
        }

        // softmax phase 1: partial row max
        float pm0 = sfr[0][0], pm1 = sfr[0][2];
        #pragma unroll
        for (int nt=0;nt<4;nt++){
            pm0 = fmaxf(pm0, fmaxf(sfr[nt][0], sfr[nt][1]));
            pm1 = fmaxf(pm1, fmaxf(sfr[nt][2], sfr[nt][3]));
        }
        pm0 = fmaxf(pm0, __shfl_xor_sync(0xffffffffu, pm0, 1));
        pm0 = fmaxf(pm0, __shfl_xor_sync(0xffffffffu, pm0, 2));
        pm1 = fmaxf(pm1, __shfl_xor_sync(0xffffffffu, pm1, 1));
        pm1 = fmaxf(pm1, __shfl_xor_sync(0xffffffffu, pm1, 2));
        if (tig == 0){
            pmax2[wc*64 + m0+g  ] = pm0;
            pmax2[wc*64 + m0+g+8] = pm1;
        }
        __syncthreads();

        // phase 2: P = exp(S - m_new), partial sums, store fp16 P
        {
            const int r0 = m0+g, r1 = m0+g+8;
            float mn0 = fmaxf(row_m[r0], fmaxf(pmax2[r0], pmax2[64+r0]));
            float mn1 = fmaxf(row_m[r1], fmaxf(pmax2[r1], pmax2[64+r1]));
            float ts0 = 0.f, ts1 = 0.f;
            #pragma unroll
            for (int nt=0;nt<4;nt++){
                int cb2 = nqk0 + nt*8 + 2*tig;
                float p00 = __expf(sfr[nt][0]-mn0), p01 = __expf(sfr[nt][1]-mn0);
                float p10 = __expf(sfr[nt][2]-mn1), p11 = __expf(sfr[nt][3]-mn1);
                ts0 += p00+p01;  ts1 += p10+p11;
                *(uint32_t*)&Pb[r0*VSTR + cb2] = f16pack(p00, p01);
                *(uint32_t*)&Pb[r1*VSTR + cb2] = f16pack(p10, p11);
            }
            ts0 += __shfl_xor_sync(0xffffffffu, ts0, 1);
            ts0 += __shfl_xor_sync(0xffffffffu, ts0, 2);
            ts1 += __shfl_xor_sync(0xffffffffu, ts1, 1);
            ts1 += __shfl_xor_sync(0xffffffffu, ts1, 2);
            if (tig == 0){ psum2[wc*64+r0] = ts0; psum2[wc*64+r1] = ts1; }
        }
        __syncthreads();

        // phase 3: row state (single writer per row)
        if (wc == 0 && tig == 0){
            #pragma unroll
            for (int h=0;h<2;h++){
                int r = m0 + g + h*8;
                float mo = row_m[r];
                float mn = fmaxf(mo, fmaxf(pmax2[r], pmax2[64+r]));
                float sc = __expf(mo - mn);
                row_sc[r] = sc;
                row_l[r]  = row_l[r]*sc + psum2[r] + psum2[64+r];
                row_m[r]  = mn;
            }
        }
        __syncthreads();

        // ---- PV: rescale accumulators, then fp16 m16n8k16 MMA ----
        float s0v[8], s1v[8];
        bool need = false;
        #pragma unroll
        for (int nt=0;nt<8;nt++){
            s0v[nt] = row_sc[nt*8 + 2*tig];
            s1v[nt] = row_sc[nt*8 + 2*tig + 1];
            need |= (s0v[nt] != 1.f) | (s1v[nt] != 1.f);
        }
        if (__ballot_sync(0xffffffffu, need)){
            #pragma unroll
            for (int mt=0;mt<2;mt++)
                #pragma unroll
                for (int nt=0;nt<8;nt++){
                    d_acc[mt][nt][0] *= s0v[nt];  d_acc[mt][nt][1] *= s1v[nt];
                    d_acc[mt][nt][2] *= s0v[nt];  d_acc[mt][nt][3] *= s1v[nt];
                }
        }
        #pragma unroll
        for (int ks=0; ks<4; ks++){
            int k0 = ks*16;
            uint32_t A0[4], A1[4];
            A0[0] = *(const uint32_t*)&Vb[(c0+g   )*VSTR + k0+2*tig  ];
            A0[1] = *(const uint32_t*)&Vb[(c0+g+8 )*VSTR + k0+2*tig  ];
            A0[2] = *(const uint32_t*)&Vb[(c0+g   )*VSTR + k0+2*tig+8];
            A0[3] = *(const uint32_t*)&Vb[(c0+g+8 )*VSTR + k0+2*tig+8];
            A1[0] = *(const uint32_t*)&Vb[(c0+g+16)*VSTR + k0+2*tig  ];
            A1[1] = *(const uint32_t*)&Vb[(c0+g+24)*VSTR + k0+2*tig  ];
            A1[2] = *(const uint32_t*)&Vb[(c0+g+16)*VSTR + k0+2*tig+8];
            A1[3] = *(const uint32_t*)&Vb[(c0+g+24)*VSTR + k0+2*tig+8];
            #pragma unroll
            for (int nt=0;nt<8;nt++){
                uint32_t b0 = *(const uint32_t*)&Pb[(nt*8+g)*VSTR + k0+2*tig  ];
                uint32_t b1 = *(const uint32_t*)&Pb[(nt*8+g)*VSTR + k0+2*tig+8];
                mma_f16(d_acc[0][nt], A0, b0, b1);
                mma_f16(d_acc[1][nt], A1, b0, b1);
            }
        }
    }

    // ---- epilogue ----
    __syncthreads();
    if (t < 64) row_rl[t] = 1.f / row_l[t];
    __syncthreads();

    const float gam = gamma[0];
    float rl0[8], rl1[8];
    #pragma unroll
    for (int nt=0;nt<8;nt++){
        rl0[nt] = row_rl[nt*8 + 2*tig];
        rl1[nt] = row_rl[nt*8 + 2*tig + 1];
    }
    const int cta = b*NQT + blockIdx.x;
    #pragma unroll
    for (int mt=0;mt<2;mt++){
        #pragma unroll
        for (int h=0;h<2;h++){
            int c = c0 + mt*16 + g + h*8;
            size_t base = ((size_t)b*CCH + c)*NPIX + i0;
            float accs = 0.f, accq = 0.f;
            #pragma unroll
            for (int nt=0;nt<8;nt++){
                int i = nt*8 + 2*tig;
                float2 xv = *(const float2*)(x + base + i);
                float y0 = gam*d_acc[mt][nt][h*2+0]*rl0[nt] + xv.x;
                float y1 = gam*d_acc[mt][nt][h*2+1]*rl1[nt] + xv.y;
                *(float2*)(g_y + base + i) = make_float2(y0, y1);
                accs += y0 + y1;
                accq += y0*y0 + y1*y1;
            }
            accs += __shfl_xor_sync(0xffffffffu, accs, 1);
            accs += __shfl_xor_sync(0xffffffffu, accs, 2);
            accq += __shfl_xor_sync(0xffffffffu, accq, 1);
            accq += __shfl_xor_sync(0xffffffffu, accq, 2);
            if (tig == 0){
                g_psum[cta*CCH + c] = accs;
                g_psq [cta*CCH + c] = accq;
            }
        }
    }
}

// ---------------- Kernel C1: BN stat reduce -------------------------------
__global__ __launch_bounds__(256) void bnstat_kernel(
    const float* __restrict__ bnw, const float* __restrict__ bnb)
{
    __shared__ float ss[256], sq[256];
    const int c = blockIdx.x, t = threadIdx.x;
    float s = g_psum[t*CCH + c] + g_psum[(t+256)*CCH + c];
    float q = g_psq [t*CCH + c] + g_psq [(t+256)*CCH + c];
    ss[t]=s; sq[t]=q;
    __syncthreads();
    for (int off=128; off>0; off>>=1){
        if (t<off){ ss[t]+=ss[t+off]; sq[t]+=sq[t+off]; }
        __syncthreads();
    }
    if (t==0){
        const float inv = 1.f/32768.f;
        float mean = ss[0]*inv;
        float var  = sq[0]*inv - mean*mean;
        float scale = bnw[c]*rsqrtf(var + 1e-5f);
        g_bn[c]       = scale;
        g_bn[CCH + c] = bnb[c] - mean*scale;
    }
}

// ---------------- Kernel C2: BN apply + ReLU ------------------------------
__global__ __launch_bounds__(256) void bnapply_kernel(float* __restrict__ out)
{
    int idx = blockIdx.x*256 + threadIdx.x;
    int c = (idx >> 10) & 255;
    float scale = g_bn[c], shift = g_bn[CCH + c];
    float4 y = ((const float4*)g_y)[idx];
    float4 o;
    o.x = fmaxf(y.x*scale + shift, 0.f);
    o.y = fmaxf(y.y*scale + shift, 0.f);
    o.z = fmaxf(y.z*scale + shift, 0.f);
    o.w = fmaxf(y.w*scale + shift, 0.f);
    ((float4*)out)[idx] = o;
}

// ---------------------------------------------------------------------------
extern "C" void kernel_launch(void* const* d_in, const int* in_sizes, int n_in,
                              void* d_out, int out_size)
{
    const float* x     = (const float*)d_in[0];
    const float* wq    = (const float*)d_in[1];
    const float* bq    = (const float*)d_in[2];
    const float* wk    = (const float*)d_in[3];
    const float* bk    = (const float*)d_in[4];
    const float* wv    = (const float*)d_in[5];
    const float* bv    = (const float*)d_in[6];
    const float* gamma = (const float*)d_in[7];
    const float* bnw   = (const float*)d_in[8];
    const float* bnb   = (const float*)d_in[9];
    float* out = (float*)d_out;

    dim3 gA(NPIX/128, 5, BATCH);
    projmma_kernel<<<gA, 256>>>(x, wq, bq, wk, bk, wv, bv);

    const int attn_smem = (256*VSTR + 64*VSTR)*2 + (4*64*QKS)*4 + (128+128+64*4)*4; // 67,584 B
    cudaFuncSetAttribute(attn_kernel, cudaFuncAttributeMaxDynamicSharedMemorySize, attn_smem);
    attn_kernel<<<dim3(NQT, BATCH), 256, attn_smem>>>(x, gamma);

    bnstat_kernel<<<CCH, 256>>>(bnw, bnb);

    bnapply_kernel<<<(BATCH*CCH*NPIX)/(256*4), 256>>>(out);
}